// round 1
// baseline (speedup 1.0000x reference)
#include <cuda_runtime.h>
#include <math_constants.h>

#define B_ 4
#define T_ 2048
#define C_ 1024
#define H_ 16
#define D_ 64
#define S_ (B_*T_)   // 8192

// Scratch (device globals: allocation-free per harness rules)
__device__ float g_q[B_*H_*T_*D_];
__device__ float g_k[B_*H_*T_*D_];
__device__ float g_v[B_*H_*T_*D_];
__device__ float g_y[S_*C_];

// ---------------------------------------------------------------------------
// 128x128x16 SGEMM, 256 threads, 8x8 register tile per thread.
// MODE 0: A = x, epilogue scatters qkv -> g_q/g_k/g_v in [B,H,T,D] layout.
// MODE 1: A = g_y, epilogue writes out[m*N+n] + bias.
// ---------------------------------------------------------------------------
template<int MODE>
__global__ __launch_bounds__(256)
void gemm128(const float* __restrict__ A,
             const float* __restrict__ W,
             const float* __restrict__ bias,
             float* __restrict__ out,
             int N, int K)
{
    __shared__ float As[16][132];   // transposed A tile, padded (16B-aligned rows)
    __shared__ float Bs[16][128];

    const int tid = threadIdx.x;
    const int bm = blockIdx.y * 128;
    const int bn = blockIdx.x * 128;
    const float* Ap = (MODE == 0) ? A : g_y;

    const int aRow = tid >> 2;           // 0..63
    const int aCol = (tid & 3) << 2;     // 0,4,8,12
    const int bRow = tid >> 5;           // 0..7
    const int bCol = (tid & 31) << 2;    // 0..124
    const int tx = tid & 15, ty = tid >> 4;

    float acc[8][8];
    #pragma unroll
    for (int i = 0; i < 8; ++i)
        #pragma unroll
        for (int j = 0; j < 8; ++j) acc[i][j] = 0.f;

    for (int k0 = 0; k0 < K; k0 += 16) {
        float4 a0 = *(const float4*)(Ap + (size_t)(bm + aRow)      * K + k0 + aCol);
        float4 a1 = *(const float4*)(Ap + (size_t)(bm + aRow + 64) * K + k0 + aCol);
        float4 b0 = *(const float4*)(W  + (size_t)(k0 + bRow)      * N + bn + bCol);
        float4 b1 = *(const float4*)(W  + (size_t)(k0 + bRow + 8)  * N + bn + bCol);

        As[aCol+0][aRow]    = a0.x; As[aCol+1][aRow]    = a0.y;
        As[aCol+2][aRow]    = a0.z; As[aCol+3][aRow]    = a0.w;
        As[aCol+0][aRow+64] = a1.x; As[aCol+1][aRow+64] = a1.y;
        As[aCol+2][aRow+64] = a1.z; As[aCol+3][aRow+64] = a1.w;
        *(float4*)&Bs[bRow][bCol]   = b0;
        *(float4*)&Bs[bRow+8][bCol] = b1;
        __syncthreads();

        #pragma unroll
        for (int k = 0; k < 16; ++k) {
            float4 ra0 = *(const float4*)&As[k][ty*8];
            float4 ra1 = *(const float4*)&As[k][ty*8+4];
            float4 rb0 = *(const float4*)&Bs[k][tx*8];
            float4 rb1 = *(const float4*)&Bs[k][tx*8+4];
            float ra[8] = {ra0.x,ra0.y,ra0.z,ra0.w,ra1.x,ra1.y,ra1.z,ra1.w};
            float rb[8] = {rb0.x,rb0.y,rb0.z,rb0.w,rb1.x,rb1.y,rb1.z,rb1.w};
            #pragma unroll
            for (int i = 0; i < 8; ++i)
                #pragma unroll
                for (int j = 0; j < 8; ++j)
                    acc[i][j] = fmaf(ra[i], rb[j], acc[i][j]);
        }
        __syncthreads();
    }

    #pragma unroll
    for (int i = 0; i < 8; ++i) {
        const int m = bm + ty*8 + i;
        #pragma unroll
        for (int j = 0; j < 8; ++j) {
            const int n = bn + tx*8 + j;
            float v = acc[i][j] + bias[n];
            if (MODE == 0) {
                const int part = n >> 10;          // 0:q 1:k 2:v
                const int cl = n & 1023;
                const int hh = cl >> 6, dd = cl & 63;
                const int bb = m >> 11, tt = m & 2047;
                float* dst = (part == 0) ? g_q : ((part == 1) ? g_k : g_v);
                dst[((((bb*H_ + hh)*T_) + tt) << 6) + dd] = v;
            } else {
                out[(size_t)m * N + n] = v;
            }
        }
    }
}

// ---------------------------------------------------------------------------
// Causal flash attention, fp32. One block per (q-tile of 64, head, batch).
// 256 threads: thread = (row r = tid/4, quad lane q4 = tid%3..). Each quad owns
// one q row: scores split 16 cols/thread (interleaved col = jj*4+q4, bank-clean),
// PV split 16 dims/thread (interleaved d = d4*16+q4*4, bank-clean).
// Row max/sum reduced across the quad with shfl_xor(1,2).
// ---------------------------------------------------------------------------
__global__ __launch_bounds__(256)
void attn_kernel()
{
    extern __shared__ float sm[];
    float* Qs = sm;                 // [64][68]
    float* Ks = sm + 64*68;
    float* Vs = sm + 2*64*68;
    float* Ss = sm + 3*64*68;

    const int qt = blockIdx.x;      // 0..31
    const int h  = blockIdx.y;
    const int b  = blockIdx.z;
    const int tid = threadIdx.x;
    const int r  = tid >> 2;        // q row within tile
    const int q4 = tid & 3;         // quad lane

    const size_t base = (size_t)((b*H_ + h) * T_) * D_;
    const float* Qb = g_q + base;
    const float* Kb = g_k + base;
    const float* Vb = g_v + base;

    // Load Q tile (coalesced float4)
    #pragma unroll
    for (int it = 0; it < 4; ++it) {
        int idx = tid + it*256;
        int row = idx >> 4, col = (idx & 15) << 2;
        *(float4*)&Qs[row*68 + col] = *(const float4*)(Qb + (qt*64 + row)*64 + col);
    }

    float o[16];
    #pragma unroll
    for (int i = 0; i < 16; ++i) o[i] = 0.f;
    float mi = -CUDART_INF_F, li = 0.f;

    for (int kt = 0; kt <= qt; ++kt) {
        __syncthreads();   // previous iteration done reading Ks/Vs (and Q visible, iter 0)
        #pragma unroll
        for (int it = 0; it < 4; ++it) {
            int idx = tid + it*256;
            int row = idx >> 4, col = (idx & 15) << 2;
            *(float4*)&Ks[row*68 + col] = *(const float4*)(Kb + (kt*64 + row)*64 + col);
            *(float4*)&Vs[row*68 + col] = *(const float4*)(Vb + (kt*64 + row)*64 + col);
        }
        __syncthreads();

        // S = Q K^T for this thread's 16 columns (col = jj*4 + q4)
        float s[16];
        #pragma unroll
        for (int jj = 0; jj < 16; ++jj) s[jj] = 0.f;
        #pragma unroll 4
        for (int k = 0; k < 64; k += 4) {
            float4 qv = *(const float4*)&Qs[r*68 + k];
            #pragma unroll
            for (int jj = 0; jj < 16; ++jj) {
                float4 kv = *(const float4*)&Ks[(jj*4 + q4)*68 + k];
                s[jj] = fmaf(qv.x, kv.x, s[jj]);
                s[jj] = fmaf(qv.y, kv.y, s[jj]);
                s[jj] = fmaf(qv.z, kv.z, s[jj]);
                s[jj] = fmaf(qv.w, kv.w, s[jj]);
            }
        }

        // scale + causal mask + running softmax update
        const bool diag = (kt == qt);
        float mt = -CUDART_INF_F;
        #pragma unroll
        for (int jj = 0; jj < 16; ++jj) {
            const int col = jj*4 + q4;
            float sv = s[jj] * 0.125f;          // 1/sqrt(64)
            if (diag && col > r) sv = -CUDART_INF_F;
            s[jj] = sv;
            mt = fmaxf(mt, sv);
        }
        mt = fmaxf(mt, __shfl_xor_sync(0xffffffffu, mt, 1));
        mt = fmaxf(mt, __shfl_xor_sync(0xffffffffu, mt, 2));
        const float mnew  = fmaxf(mi, mt);
        const float alpha = __expf(mi - mnew);  // exp(-inf)=0 on first tile
        float ls = 0.f;
        #pragma unroll
        for (int jj = 0; jj < 16; ++jj) {
            float p = __expf(s[jj] - mnew);
            ls += p;
            Ss[r*68 + jj*4 + q4] = p;
        }
        ls += __shfl_xor_sync(0xffffffffu, ls, 1);
        ls += __shfl_xor_sync(0xffffffffu, ls, 2);
        li = li * alpha + ls;
        mi = mnew;
        #pragma unroll
        for (int i = 0; i < 16; ++i) o[i] *= alpha;
        __syncwarp();   // Ss written/read within the same warp's quads

        // O += P V for this thread's 16 dims (d = d4*16 + q4*4 + c)
        #pragma unroll 8
        for (int j = 0; j < 64; ++j) {
            const float p = Ss[r*68 + j];
            #pragma unroll
            for (int d4 = 0; d4 < 4; ++d4) {
                float4 vv = *(const float4*)&Vs[j*68 + d4*16 + q4*4];
                o[d4*4+0] = fmaf(p, vv.x, o[d4*4+0]);
                o[d4*4+1] = fmaf(p, vv.y, o[d4*4+1]);
                o[d4*4+2] = fmaf(p, vv.z, o[d4*4+2]);
                o[d4*4+3] = fmaf(p, vv.w, o[d4*4+3]);
            }
        }
    }

    // finalize: y[b][t][h*64+d] = o/l  (re-fused to [B,T,C] for the proj GEMM)
    const float inv = __frcp_rn(li);
    const int qi = qt*64 + r;
    float* yrow = g_y + (size_t)(b*T_ + qi)*C_ + h*D_;
    #pragma unroll
    for (int d4 = 0; d4 < 4; ++d4) {
        float4 ov = make_float4(o[d4*4+0]*inv, o[d4*4+1]*inv,
                                o[d4*4+2]*inv, o[d4*4+3]*inv);
        *(float4*)&yrow[d4*16 + q4*4] = ov;
    }
}

// ---------------------------------------------------------------------------
extern "C" void kernel_launch(void* const* d_in, const int* in_sizes, int n_in,
                              void* d_out, int out_size)
{
    const float* x      = (const float*)d_in[0];
    const float* w_attn = (const float*)d_in[1];
    const float* b_attn = (const float*)d_in[2];
    const float* w_proj = (const float*)d_in[3];
    const float* b_proj = (const float*)d_in[4];
    float* out = (float*)d_out;

    // 1) QKV GEMM: [8192,1024] @ [1024,3072], scatter to g_q/g_k/g_v
    gemm128<0><<<dim3(3*C_/128, S_/128), 256>>>(x, w_attn, b_attn, nullptr, 3*C_, C_);

    // 2) Causal flash attention -> g_y [B,T,C]
    const int smem_bytes = 4 * 64 * 68 * (int)sizeof(float);   // 69632 B
    cudaFuncSetAttribute(attn_kernel, cudaFuncAttributeMaxDynamicSharedMemorySize, smem_bytes);
    attn_kernel<<<dim3(T_/64, H_, B_), 256, smem_bytes>>>();

    // 3) Proj GEMM: [8192,1024] @ [1024,1024] + bias -> out
    gemm128<1><<<dim3(C_/128, S_/128), 256>>>(nullptr, w_proj, b_proj, out, C_, C_);
}

// round 3
// speedup vs baseline: 1.3822x; 1.3822x over previous
#include <cuda_runtime.h>
#include <math_constants.h>
#include <cstdint>

#define B_ 4
#define T_ 2048
#define C_ 1024
#define H_ 16
#define D_ 64
#define S_ (B_*T_)   // 8192

// Scratch (device globals: allocation-free per harness rules)
__device__ float g_q[B_*H_*T_*D_];
__device__ float g_k[B_*H_*T_*D_];
__device__ float g_v[B_*H_*T_*D_];
__device__ float g_y[S_*C_];

__device__ __forceinline__ uint32_t f2tf32(float f) {
    uint32_t r;
    asm("cvt.rna.tf32.f32 %0, %1;" : "=r"(r) : "f"(f));
    return r;
}

// mma.sync m16n8k8 tf32: D = A*B + D.  A row-major 16x8, B col-major 8x8.
__device__ __forceinline__ void mma_tf32(float c[4],
                                         uint32_t a0, uint32_t a1, uint32_t a2, uint32_t a3,
                                         uint32_t b0, uint32_t b1) {
    asm volatile(
        "mma.sync.aligned.m16n8k8.row.col.f32.tf32.tf32.f32 "
        "{%0,%1,%2,%3}, {%4,%5,%6,%7}, {%8,%9}, {%0,%1,%2,%3};"
        : "+f"(c[0]), "+f"(c[1]), "+f"(c[2]), "+f"(c[3])
        : "r"(a0), "r"(a1), "r"(a2), "r"(a3), "r"(b0), "r"(b1));
}

// ---------------------------------------------------------------------------
// TF32 tensor-core GEMM (mma.sync), 128x128 CTA tile, 8 warps of 64x32,
// K-chunks of 32, double-buffered SMEM, register-staged global prefetch.
// Row stride 36 words: fragment LDS bank = g*4+tig = lane id (conflict-free),
// and 36*4=144 bytes is 16B-aligned so writers use STS.128.
// MODE 0: A = x, epilogue scatters to g_q/g_k/g_v.  MODE 1: A = g_y -> out.
// ---------------------------------------------------------------------------
#define PW 36                    // padded row stride in words
#define ABUF_W (128*PW)          // 4608 words per A (or B) tile
#define BUF_W  (2*ABUF_W)        // 9216 words per double-buffer half

template<int MODE>
__global__ __launch_bounds__(256)
void gemm_mma(const float* __restrict__ A,
              const float* __restrict__ W,
              const float* __restrict__ bias,
              float* __restrict__ out,
              int N, int K)
{
    extern __shared__ uint32_t sm4[];   // [2][A:4608 | B:4608] words = 73728 B

    const int tid = threadIdx.x;
    const int wid = tid >> 5, lane = tid & 31;
    const int g = lane >> 2, tig = lane & 3;
    const int wm = (wid & 1) * 64;        // warp row offset in CTA tile
    const int wn = (wid >> 1) * 32;       // warp col offset
    const int bm = blockIdx.y * 128, bn = blockIdx.x * 128;
    const float* Ap = (MODE == 0) ? A : g_y;

    float acc[4][4][4];
    #pragma unroll
    for (int i = 0; i < 4; ++i)
        #pragma unroll
        for (int j = 0; j < 4; ++j)
            #pragma unroll
            for (int k = 0; k < 4; ++k) acc[i][j][k] = 0.f;

    // per-thread global-load coordinates
    const int a_row = tid >> 3, a_kq = tid & 7;      // +i*256: rows step 32
    const int b_nl = tid & 127, b_kq = tid >> 7;     // +i*256: kq steps 2

    float4 astg[4];
    float  bstg[4][4];

    const int nch = K / 32;

    // ---- load chunk c into stage registers ----
    auto LOAD = [&](int c) {
        const int k0 = c * 32;
        #pragma unroll
        for (int i = 0; i < 4; ++i) {
            const int row = a_row + i * 32;
            astg[i] = *(const float4*)(Ap + (size_t)(bm + row) * K + k0 + a_kq * 4);
        }
        #pragma unroll
        for (int i = 0; i < 4; ++i) {
            const int kq = b_kq + i * 2;             // 0..7
            const float* src = W + (size_t)(k0 + kq * 4) * N + bn + b_nl;
            #pragma unroll
            for (int j = 0; j < 4; ++j) bstg[i][j] = src[(size_t)j * N];
        }
    };
    // ---- convert + store stage registers into smem buffer ----
    auto STORE = [&](int buf) {
        uint32_t* Asm = sm4 + buf * BUF_W;
        uint32_t* Bsm = Asm + ABUF_W;
        #pragma unroll
        for (int i = 0; i < 4; ++i) {
            const int row = a_row + i * 32;
            uint4 w;
            w.x = f2tf32(astg[i].x); w.y = f2tf32(astg[i].y);
            w.z = f2tf32(astg[i].z); w.w = f2tf32(astg[i].w);
            *(uint4*)&Asm[row * PW + a_kq * 4] = w;          // 144B row stride: 16B aligned
        }
        #pragma unroll
        for (int i = 0; i < 4; ++i) {
            const int kq = b_kq + i * 2;
            uint4 w;
            w.x = f2tf32(bstg[i][0]); w.y = f2tf32(bstg[i][1]);
            w.z = f2tf32(bstg[i][2]); w.w = f2tf32(bstg[i][3]);
            *(uint4*)&Bsm[b_nl * PW + kq * 4] = w;
        }
    };
    // ---- tensor-core compute on smem buffer ----
    auto COMPUTE = [&](int buf) {
        const uint32_t* As = sm4 + buf * BUF_W;
        const uint32_t* Bs = As + ABUF_W;
        #pragma unroll
        for (int ks = 0; ks < 4; ++ks) {
            const int kc = ks * 8 + tig;
            uint32_t af[4][4];
            #pragma unroll
            for (int mf = 0; mf < 4; ++mf) {
                const int r0 = wm + mf * 16 + g;
                af[mf][0] = As[r0 * PW + kc];
                af[mf][1] = As[(r0 + 8) * PW + kc];
                af[mf][2] = As[r0 * PW + kc + 4];
                af[mf][3] = As[(r0 + 8) * PW + kc + 4];
            }
            uint32_t bf[4][2];
            #pragma unroll
            for (int nf = 0; nf < 4; ++nf) {
                const int n0 = wn + nf * 8 + g;
                bf[nf][0] = Bs[n0 * PW + kc];
                bf[nf][1] = Bs[n0 * PW + kc + 4];
            }
            #pragma unroll
            for (int mf = 0; mf < 4; ++mf)
                #pragma unroll
                for (int nf = 0; nf < 4; ++nf)
                    mma_tf32(acc[mf][nf], af[mf][0], af[mf][1], af[mf][2], af[mf][3],
                             bf[nf][0], bf[nf][1]);
        }
    };

    LOAD(0);
    STORE(0);
    __syncthreads();

    for (int c = 0; c < nch; ++c) {
        if (c + 1 < nch) LOAD(c + 1);       // LDGs in flight during compute
        COMPUTE(c & 1);
        if (c + 1 < nch) STORE((c + 1) & 1);
        __syncthreads();
    }

    // ---- epilogue: fragments -> global (+bias) ----
    #pragma unroll
    for (int mf = 0; mf < 4; ++mf) {
        const int r0 = bm + wm + mf * 16 + g;
        #pragma unroll
        for (int nf = 0; nf < 4; ++nf) {
            const int n0 = bn + wn + nf * 8 + tig * 2;
            const float bv0 = bias[n0], bv1 = bias[n0 + 1];
            const float v00 = acc[mf][nf][0] + bv0, v01 = acc[mf][nf][1] + bv1;
            const float v10 = acc[mf][nf][2] + bv0, v11 = acc[mf][nf][3] + bv1;
            if (MODE == 0) {
                const int part = n0 >> 10;               // 0:q 1:k 2:v
                const int cl = n0 & 1023;
                const int hh = cl >> 6, dd = cl & 63;    // dd even; dd,dd+1 same head
                float* dst = (part == 0) ? g_q : ((part == 1) ? g_k : g_v);
                const int bb0 = r0 >> 11, tt0 = r0 & 2047;
                const int r1 = r0 + 8;
                const int bb1 = r1 >> 11, tt1 = r1 & 2047;
                *(float2*)&dst[((((bb0 * H_ + hh) * T_) + tt0) << 6) + dd] = make_float2(v00, v01);
                *(float2*)&dst[((((bb1 * H_ + hh) * T_) + tt1) << 6) + dd] = make_float2(v10, v11);
            } else {
                *(float2*)&out[(size_t)r0 * N + n0]       = make_float2(v00, v01);
                *(float2*)&out[(size_t)(r0 + 8) * N + n0] = make_float2(v10, v11);
            }
        }
    }
}

// ---------------------------------------------------------------------------
// Causal flash attention, fp32 SIMT (unchanged from the R1 passing version).
// ---------------------------------------------------------------------------
__global__ __launch_bounds__(256)
void attn_kernel()
{
    extern __shared__ float smf[];
    float* Qs = smf;                 // [64][68]
    float* Ks = smf + 64*68;
    float* Vs = smf + 2*64*68;
    float* Ss = smf + 3*64*68;

    const int qt = blockIdx.x;
    const int h  = blockIdx.y;
    const int b  = blockIdx.z;
    const int tid = threadIdx.x;
    const int r  = tid >> 2;
    const int q4 = tid & 3;

    const size_t base = (size_t)((b*H_ + h) * T_) * D_;
    const float* Qb = g_q + base;
    const float* Kb = g_k + base;
    const float* Vb = g_v + base;

    #pragma unroll
    for (int it = 0; it < 4; ++it) {
        int idx = tid + it*256;
        int row = idx >> 4, col = (idx & 15) << 2;
        *(float4*)&Qs[row*68 + col] = *(const float4*)(Qb + (qt*64 + row)*64 + col);
    }

    float o[16];
    #pragma unroll
    for (int i = 0; i < 16; ++i) o[i] = 0.f;
    float mi = -CUDART_INF_F, li = 0.f;

    for (int kt = 0; kt <= qt; ++kt) {
        __syncthreads();
        #pragma unroll
        for (int it = 0; it < 4; ++it) {
            int idx = tid + it*256;
            int row = idx >> 4, col = (idx & 15) << 2;
            *(float4*)&Ks[row*68 + col] = *(const float4*)(Kb + (kt*64 + row)*64 + col);
            *(float4*)&Vs[row*68 + col] = *(const float4*)(Vb + (kt*64 + row)*64 + col);
        }
        __syncthreads();

        float s[16];
        #pragma unroll
        for (int jj = 0; jj < 16; ++jj) s[jj] = 0.f;
        #pragma unroll 4
        for (int k = 0; k < 64; k += 4) {
            float4 qv = *(const float4*)&Qs[r*68 + k];
            #pragma unroll
            for (int jj = 0; jj < 16; ++jj) {
                float4 kv = *(const float4*)&Ks[(jj*4 + q4)*68 + k];
                s[jj] = fmaf(qv.x, kv.x, s[jj]);
                s[jj] = fmaf(qv.y, kv.y, s[jj]);
                s[jj] = fmaf(qv.z, kv.z, s[jj]);
                s[jj] = fmaf(qv.w, kv.w, s[jj]);
            }
        }

        const bool diag = (kt == qt);
        float mt = -CUDART_INF_F;
        #pragma unroll
        for (int jj = 0; jj < 16; ++jj) {
            const int col = jj*4 + q4;
            float sv = s[jj] * 0.125f;
            if (diag && col > r) sv = -CUDART_INF_F;
            s[jj] = sv;
            mt = fmaxf(mt, sv);
        }
        mt = fmaxf(mt, __shfl_xor_sync(0xffffffffu, mt, 1));
        mt = fmaxf(mt, __shfl_xor_sync(0xffffffffu, mt, 2));
        const float mnew  = fmaxf(mi, mt);
        const float alpha = __expf(mi - mnew);
        float ls = 0.f;
        #pragma unroll
        for (int jj = 0; jj < 16; ++jj) {
            float p = __expf(s[jj] - mnew);
            ls += p;
            Ss[r*68 + jj*4 + q4] = p;
        }
        ls += __shfl_xor_sync(0xffffffffu, ls, 1);
        ls += __shfl_xor_sync(0xffffffffu, ls, 2);
        li = li * alpha + ls;
        mi = mnew;
        #pragma unroll
        for (int i = 0; i < 16; ++i) o[i] *= alpha;
        __syncwarp();

        #pragma unroll 8
        for (int j = 0; j < 64; ++j) {
            const float p = Ss[r*68 + j];
            #pragma unroll
            for (int d4 = 0; d4 < 4; ++d4) {
                float4 vv = *(const float4*)&Vs[j*68 + d4*16 + q4*4];
                o[d4*4+0] = fmaf(p, vv.x, o[d4*4+0]);
                o[d4*4+1] = fmaf(p, vv.y, o[d4*4+1]);
                o[d4*4+2] = fmaf(p, vv.z, o[d4*4+2]);
                o[d4*4+3] = fmaf(p, vv.w, o[d4*4+3]);
            }
        }
    }

    const float inv = __frcp_rn(li);
    const int qi = qt*64 + r;
    float* yrow = g_y + (size_t)(b*T_ + qi)*C_ + h*D_;
    #pragma unroll
    for (int d4 = 0; d4 < 4; ++d4) {
        float4 ov = make_float4(o[d4*4+0]*inv, o[d4*4+1]*inv,
                                o[d4*4+2]*inv, o[d4*4+3]*inv);
        *(float4*)&yrow[d4*16 + q4*4] = ov;
    }
}

// ---------------------------------------------------------------------------
extern "C" void kernel_launch(void* const* d_in, const int* in_sizes, int n_in,
                              void* d_out, int out_size)
{
    const float* x      = (const float*)d_in[0];
    const float* w_attn = (const float*)d_in[1];
    const float* b_attn = (const float*)d_in[2];
    const float* w_proj = (const float*)d_in[3];
    const float* b_proj = (const float*)d_in[4];
    float* out = (float*)d_out;

    const int gemm_smem = 2 * BUF_W * (int)sizeof(uint32_t);   // 73728 B
    cudaFuncSetAttribute(gemm_mma<0>, cudaFuncAttributeMaxDynamicSharedMemorySize, gemm_smem);
    cudaFuncSetAttribute(gemm_mma<1>, cudaFuncAttributeMaxDynamicSharedMemorySize, gemm_smem);

    // 1) QKV GEMM (tf32 mma.sync): [8192,1024] @ [1024,3072] -> g_q/g_k/g_v
    gemm_mma<0><<<dim3(3*C_/128, S_/128), 256, gemm_smem>>>(x, w_attn, b_attn, nullptr, 3*C_, C_);

    // 2) Causal flash attention -> g_y [B,T,C]
    const int attn_smem = 4 * 64 * 68 * (int)sizeof(float);
    cudaFuncSetAttribute(attn_kernel, cudaFuncAttributeMaxDynamicSharedMemorySize, attn_smem);
    attn_kernel<<<dim3(T_/64, H_, B_), 256, attn_smem>>>();

    // 3) Proj GEMM (tf32 mma.sync): [8192,1024] @ [1024,1024] + bias -> out
    gemm_mma<1><<<dim3(C_/128, S_/128), 256, gemm_smem>>>(nullptr, w_proj, b_proj, out, C_, C_);
}

// round 4
// speedup vs baseline: 2.8528x; 2.0640x over previous
#include <cuda_runtime.h>
#include <math_constants.h>
#include <cstdint>

#define B_ 4
#define T_ 2048
#define C_ 1024
#define H_ 16
#define D_ 64
#define S_ (B_*T_)   // 8192

// Scratch (device globals: allocation-free per harness rules)
// q/k/v stored as tf32 hi/lo planes (3xTF32 split), layout [B,H,T,D].
__device__ uint32_t g_qhi[B_*H_*T_*D_];
__device__ uint32_t g_qlo[B_*H_*T_*D_];
__device__ uint32_t g_khi[B_*H_*T_*D_];
__device__ uint32_t g_klo[B_*H_*T_*D_];
__device__ uint32_t g_vhi[B_*H_*T_*D_];
__device__ uint32_t g_vlo[B_*H_*T_*D_];
__device__ float    g_y[S_*C_];

__device__ __forceinline__ uint32_t f2tf32(float f) {
    uint32_t r;
    asm("cvt.rna.tf32.f32 %0, %1;" : "=r"(r) : "f"(f));
    return r;
}

// mma.sync m16n8k8 tf32: D += A*B.  A row-major 16x8, B col-major 8x8.
// Frag maps (g=lane>>2, tig=lane&3):
//  A: a0=(g,tig) a1=(g+8,tig) a2=(g,tig+4) a3=(g+8,tig+4)
//  B: b0=(k=tig,n=g) b1=(k=tig+4,n=g)
//  C: c0=(g,2tig) c1=(g,2tig+1) c2=(g+8,2tig) c3=(g+8,2tig+1)
__device__ __forceinline__ void mma_tf32(float c[4],
                                         uint32_t a0, uint32_t a1, uint32_t a2, uint32_t a3,
                                         uint32_t b0, uint32_t b1) {
    asm volatile(
        "mma.sync.aligned.m16n8k8.row.col.f32.tf32.tf32.f32 "
        "{%0,%1,%2,%3}, {%4,%5,%6,%7}, {%8,%9}, {%0,%1,%2,%3};"
        : "+f"(c[0]), "+f"(c[1]), "+f"(c[2]), "+f"(c[3])
        : "r"(a0), "r"(a1), "r"(a2), "r"(a3), "r"(b0), "r"(b1));
}

// ---------------------------------------------------------------------------
// TF32 tensor-core GEMM (mma.sync), 128x128 CTA tile, 8 warps of 64x32.
// MODE 0: A = x, epilogue splits qkv into tf32 hi/lo planes (q scaled 1/8).
// MODE 1: A = g_y, epilogue writes fp32 out + bias.
// ---------------------------------------------------------------------------
#define PW 36
#define ABUF_W (128*PW)
#define BUF_W  (2*ABUF_W)

template<int MODE>
__global__ __launch_bounds__(256)
void gemm_mma(const float* __restrict__ A,
              const float* __restrict__ W,
              const float* __restrict__ bias,
              float* __restrict__ out,
              int N, int K)
{
    extern __shared__ uint32_t sm4[];

    const int tid = threadIdx.x;
    const int wid = tid >> 5, lane = tid & 31;
    const int g = lane >> 2, tig = lane & 3;
    const int wm = (wid & 1) * 64;
    const int wn = (wid >> 1) * 32;
    const int bm = blockIdx.y * 128, bn = blockIdx.x * 128;
    const float* Ap = (MODE == 0) ? A : g_y;

    float acc[4][4][4];
    #pragma unroll
    for (int i = 0; i < 4; ++i)
        #pragma unroll
        for (int j = 0; j < 4; ++j)
            #pragma unroll
            for (int k = 0; k < 4; ++k) acc[i][j][k] = 0.f;

    const int a_row = tid >> 3, a_kq = tid & 7;
    const int b_nl = tid & 127, b_kq = tid >> 7;

    float4 astg[4];
    float  bstg[4][4];
    const int nch = K / 32;

    auto LOAD = [&](int c) {
        const int k0 = c * 32;
        #pragma unroll
        for (int i = 0; i < 4; ++i) {
            const int row = a_row + i * 32;
            astg[i] = *(const float4*)(Ap + (size_t)(bm + row) * K + k0 + a_kq * 4);
        }
        #pragma unroll
        for (int i = 0; i < 4; ++i) {
            const int kq = b_kq + i * 2;
            const float* src = W + (size_t)(k0 + kq * 4) * N + bn + b_nl;
            #pragma unroll
            for (int j = 0; j < 4; ++j) bstg[i][j] = src[(size_t)j * N];
        }
    };
    auto STORE = [&](int buf) {
        uint32_t* Asm = sm4 + buf * BUF_W;
        uint32_t* Bsm = Asm + ABUF_W;
        #pragma unroll
        for (int i = 0; i < 4; ++i) {
            const int row = a_row + i * 32;
            uint4 w;
            w.x = f2tf32(astg[i].x); w.y = f2tf32(astg[i].y);
            w.z = f2tf32(astg[i].z); w.w = f2tf32(astg[i].w);
            *(uint4*)&Asm[row * PW + a_kq * 4] = w;
        }
        #pragma unroll
        for (int i = 0; i < 4; ++i) {
            const int kq = b_kq + i * 2;
            uint4 w;
            w.x = f2tf32(bstg[i][0]); w.y = f2tf32(bstg[i][1]);
            w.z = f2tf32(bstg[i][2]); w.w = f2tf32(bstg[i][3]);
            *(uint4*)&Bsm[b_nl * PW + kq * 4] = w;
        }
    };
    auto COMPUTE = [&](int buf) {
        const uint32_t* As = sm4 + buf * BUF_W;
        const uint32_t* Bs = As + ABUF_W;
        #pragma unroll
        for (int ks = 0; ks < 4; ++ks) {
            const int kc = ks * 8 + tig;
            uint32_t af[4][4];
            #pragma unroll
            for (int mf = 0; mf < 4; ++mf) {
                const int r0 = wm + mf * 16 + g;
                af[mf][0] = As[r0 * PW + kc];
                af[mf][1] = As[(r0 + 8) * PW + kc];
                af[mf][2] = As[r0 * PW + kc + 4];
                af[mf][3] = As[(r0 + 8) * PW + kc + 4];
            }
            uint32_t bf[4][2];
            #pragma unroll
            for (int nf = 0; nf < 4; ++nf) {
                const int n0 = wn + nf * 8 + g;
                bf[nf][0] = Bs[n0 * PW + kc];
                bf[nf][1] = Bs[n0 * PW + kc + 4];
            }
            #pragma unroll
            for (int mf = 0; mf < 4; ++mf)
                #pragma unroll
                for (int nf = 0; nf < 4; ++nf)
                    mma_tf32(acc[mf][nf], af[mf][0], af[mf][1], af[mf][2], af[mf][3],
                             bf[nf][0], bf[nf][1]);
        }
    };

    LOAD(0);
    STORE(0);
    __syncthreads();

    for (int c = 0; c < nch; ++c) {
        if (c + 1 < nch) LOAD(c + 1);
        COMPUTE(c & 1);
        if (c + 1 < nch) STORE((c + 1) & 1);
        __syncthreads();
    }

    #pragma unroll
    for (int mf = 0; mf < 4; ++mf) {
        const int r0 = bm + wm + mf * 16 + g;
        #pragma unroll
        for (int nf = 0; nf < 4; ++nf) {
            const int n0 = bn + wn + nf * 8 + tig * 2;
            const float bv0 = bias[n0], bv1 = bias[n0 + 1];
            float v00 = acc[mf][nf][0] + bv0, v01 = acc[mf][nf][1] + bv1;
            float v10 = acc[mf][nf][2] + bv0, v11 = acc[mf][nf][3] + bv1;
            if (MODE == 0) {
                const int part = n0 >> 10;               // 0:q 1:k 2:v
                const int cl = n0 & 1023;
                const int hh = cl >> 6, dd = cl & 63;
                uint32_t *dh, *dl;
                if (part == 0) { dh = g_qhi; dl = g_qlo; v00 *= 0.125f; v01 *= 0.125f; v10 *= 0.125f; v11 *= 0.125f; }
                else if (part == 1) { dh = g_khi; dl = g_klo; }
                else { dh = g_vhi; dl = g_vlo; }
                const uint32_t h00 = f2tf32(v00), h01 = f2tf32(v01);
                const uint32_t h10 = f2tf32(v10), h11 = f2tf32(v11);
                const uint32_t l00 = f2tf32(v00 - __uint_as_float(h00));
                const uint32_t l01 = f2tf32(v01 - __uint_as_float(h01));
                const uint32_t l10 = f2tf32(v10 - __uint_as_float(h10));
                const uint32_t l11 = f2tf32(v11 - __uint_as_float(h11));
                const int bb0 = r0 >> 11, tt0 = r0 & 2047;
                const int r1 = r0 + 8;
                const int bb1 = r1 >> 11, tt1 = r1 & 2047;
                const int i0 = ((((bb0 * H_ + hh) * T_) + tt0) << 6) + dd;
                const int i1 = ((((bb1 * H_ + hh) * T_) + tt1) << 6) + dd;
                *(uint2*)&dh[i0] = make_uint2(h00, h01);
                *(uint2*)&dl[i0] = make_uint2(l00, l01);
                *(uint2*)&dh[i1] = make_uint2(h10, h11);
                *(uint2*)&dl[i1] = make_uint2(l10, l11);
            } else {
                *(float2*)&out[(size_t)r0 * N + n0]       = make_float2(v00, v01);
                *(float2*)&out[(size_t)(r0 + 8) * N + n0] = make_float2(v10, v11);
            }
        }
    }
}

// ---------------------------------------------------------------------------
// Tensor-core causal flash attention (mma.sync tf32, 3xTF32 both products).
// CTA: 128 q-rows for one (b,h). 8 warps x 16 rows. K/V tiles of 64 rows,
// 4 tf32 planes (khi,klo,vhi,vlo) in smem, cp.async double-buffered.
// Q hi/lo fragments live in registers; P round-trips smem within-warp.
// ---------------------------------------------------------------------------
#define BQ 128
#define PWK 68
#define PWP 72
#define KVW (64*PWK)          // words per plane
#define BUFW (4*KVW)          // words per buffer (4 planes)
#define PS_OFF (2*BUFW)
#define ATTN_SMEM_BYTES ((PS_OFF + BQ*PWP)*4)   // 176128 B

__global__ __launch_bounds__(256, 1)
void attn_mma()
{
    extern __shared__ uint32_t sw[];
    uint32_t sbase;
    asm("{ .reg .u64 t; cvta.to.shared.u64 t, %1; cvt.u32.u64 %0, t; }"
        : "=r"(sbase) : "l"(sw));

    const int tid = threadIdx.x, wid = tid >> 5, lane = tid & 31;
    const int g = lane >> 2, tig = lane & 3;
    const int qt = blockIdx.x, h = blockIdx.y, b = blockIdx.z;
    const int qbase = qt * BQ;
    const size_t pb = (size_t)((b * H_ + h) * T_) * D_;

    // Q fragments (hi/lo), register-resident: rows qbase+wid*16+{g,g+8}
    uint32_t aqh[8][4], aql[8][4];
    {
        const uint32_t* qh = g_qhi + pb;
        const uint32_t* ql = g_qlo + pb;
        const int r0 = qbase + wid * 16 + g;
        #pragma unroll
        for (int ks = 0; ks < 8; ++ks) {
            const int c = ks * 8 + tig;
            aqh[ks][0] = qh[(size_t)r0 * 64 + c];
            aqh[ks][1] = qh[(size_t)(r0 + 8) * 64 + c];
            aqh[ks][2] = qh[(size_t)r0 * 64 + c + 4];
            aqh[ks][3] = qh[(size_t)(r0 + 8) * 64 + c + 4];
            aql[ks][0] = ql[(size_t)r0 * 64 + c];
            aql[ks][1] = ql[(size_t)(r0 + 8) * 64 + c];
            aql[ks][2] = ql[(size_t)r0 * 64 + c + 4];
            aql[ks][3] = ql[(size_t)(r0 + 8) * 64 + c + 4];
        }
    }

    float oacc[8][4];
    #pragma unroll
    for (int nf = 0; nf < 8; ++nf)
        #pragma unroll
        for (int j = 0; j < 4; ++j) oacc[nf][j] = 0.f;
    float m0 = -CUDART_INF_F, m1 = -CUDART_INF_F, l0 = 0.f, l1 = 0.f;

    const int nkt = 2 * qt + 2;

    // cp.async tile loader: 4 planes x 64x64 words into padded smem rows
    auto ISSUE = [&](int kt, int buf) {
        #pragma unroll
        for (int p = 0; p < 4; ++p) {
            const uint32_t* plane =
                (p == 0) ? g_khi : (p == 1) ? g_klo : (p == 2) ? g_vhi : g_vlo;
            #pragma unroll
            for (int i = 0; i < 4; ++i) {
                const int idx = tid + i * 256;
                const int row = idx >> 4, c4 = (idx & 15) << 2;
                const uint32_t* src = plane + pb + (size_t)(kt * 64 + row) * 64 + c4;
                const uint32_t dst = sbase + (buf * BUFW + p * KVW + row * PWK + c4) * 4;
                asm volatile("cp.async.cg.shared.global [%0], [%1], 16;"
                             :: "r"(dst), "l"(src) : "memory");
            }
        }
        asm volatile("cp.async.commit_group;" ::: "memory");
    };

    ISSUE(0, 0);
    if (nkt > 1) ISSUE(1, 1);

    for (int kt = 0; kt < nkt; ++kt) {
        if (kt < nkt - 1) asm volatile("cp.async.wait_group 1;" ::: "memory");
        else              asm volatile("cp.async.wait_group 0;" ::: "memory");
        __syncthreads();

        const uint32_t* KH = sw + (kt & 1) * BUFW;
        const uint32_t* KL = KH + KVW;
        const uint32_t* VH = KH + 2 * KVW;
        const uint32_t* VL = KH + 3 * KVW;
        float* Ps = (float*)(sw + PS_OFF);

        // ---- S = Q K^T (3xTF32) ----
        float sa[8][4];
        #pragma unroll
        for (int nf = 0; nf < 8; ++nf)
            #pragma unroll
            for (int j = 0; j < 4; ++j) sa[nf][j] = 0.f;
        #pragma unroll
        for (int ks = 0; ks < 8; ++ks) {
            #pragma unroll
            for (int nf = 0; nf < 8; ++nf) {
                const int bo = (nf * 8 + g) * PWK + ks * 8 + tig;
                const uint32_t bh0 = KH[bo], bh1 = KH[bo + 4];
                const uint32_t bl0 = KL[bo], bl1 = KL[bo + 4];
                mma_tf32(sa[nf], aqh[ks][0], aqh[ks][1], aqh[ks][2], aqh[ks][3], bh0, bh1);
                mma_tf32(sa[nf], aqh[ks][0], aqh[ks][1], aqh[ks][2], aqh[ks][3], bl0, bl1);
                mma_tf32(sa[nf], aql[ks][0], aql[ks][1], aql[ks][2], aql[ks][3], bh0, bh1);
            }
        }

        // ---- causal mask (only the last two k-tiles intersect the diagonal) ----
        const int ktb = kt * 64;
        const int rg0 = qbase + wid * 16 + g, rg1 = rg0 + 8;
        if (ktb >= qbase) {
            #pragma unroll
            for (int nf = 0; nf < 8; ++nf) {
                const int c0 = ktb + nf * 8 + 2 * tig;
                if (c0     > rg0) sa[nf][0] = -CUDART_INF_F;
                if (c0 + 1 > rg0) sa[nf][1] = -CUDART_INF_F;
                if (c0     > rg1) sa[nf][2] = -CUDART_INF_F;
                if (c0 + 1 > rg1) sa[nf][3] = -CUDART_INF_F;
            }
        }

        // ---- running softmax (rows g and g+8; row spread across the tig quad) ----
        float mt0 = -CUDART_INF_F, mt1 = -CUDART_INF_F;
        #pragma unroll
        for (int nf = 0; nf < 8; ++nf) {
            mt0 = fmaxf(mt0, fmaxf(sa[nf][0], sa[nf][1]));
            mt1 = fmaxf(mt1, fmaxf(sa[nf][2], sa[nf][3]));
        }
        mt0 = fmaxf(mt0, __shfl_xor_sync(0xffffffffu, mt0, 1));
        mt0 = fmaxf(mt0, __shfl_xor_sync(0xffffffffu, mt0, 2));
        mt1 = fmaxf(mt1, __shfl_xor_sync(0xffffffffu, mt1, 1));
        mt1 = fmaxf(mt1, __shfl_xor_sync(0xffffffffu, mt1, 2));
        const float mn0 = fmaxf(m0, mt0), mn1 = fmaxf(m1, mt1);
        const float al0 = __expf(m0 - mn0), al1 = __expf(m1 - mn1);
        float ls0 = 0.f, ls1 = 0.f;
        const int prow = wid * 16 + g;
        #pragma unroll
        for (int nf = 0; nf < 8; ++nf) {
            const float p0 = __expf(sa[nf][0] - mn0), p1 = __expf(sa[nf][1] - mn0);
            const float p2 = __expf(sa[nf][2] - mn1), p3 = __expf(sa[nf][3] - mn1);
            ls0 += p0 + p1; ls1 += p2 + p3;
            *(float2*)&Ps[prow * PWP + nf * 8 + 2 * tig]       = make_float2(p0, p1);
            *(float2*)&Ps[(prow + 8) * PWP + nf * 8 + 2 * tig] = make_float2(p2, p3);
        }
        ls0 += __shfl_xor_sync(0xffffffffu, ls0, 1);
        ls0 += __shfl_xor_sync(0xffffffffu, ls0, 2);
        ls1 += __shfl_xor_sync(0xffffffffu, ls1, 1);
        ls1 += __shfl_xor_sync(0xffffffffu, ls1, 2);
        l0 = l0 * al0 + ls0;
        l1 = l1 * al1 + ls1;
        m0 = mn0; m1 = mn1;
        #pragma unroll
        for (int nf = 0; nf < 8; ++nf) {
            oacc[nf][0] *= al0; oacc[nf][1] *= al0;
            oacc[nf][2] *= al1; oacc[nf][3] *= al1;
        }
        __syncwarp();   // P rows are warp-private: warp-level barrier suffices

        // ---- O += P V (3xTF32; P hi/lo split in registers) ----
        #pragma unroll
        for (int ks = 0; ks < 8; ++ks) {
            const int kc = ks * 8 + tig;
            const float pf0 = Ps[prow * PWP + kc];
            const float pf1 = Ps[(prow + 8) * PWP + kc];
            const float pf2 = Ps[prow * PWP + kc + 4];
            const float pf3 = Ps[(prow + 8) * PWP + kc + 4];
            const uint32_t ph0 = f2tf32(pf0), ph1 = f2tf32(pf1);
            const uint32_t ph2 = f2tf32(pf2), ph3 = f2tf32(pf3);
            const uint32_t pl0 = f2tf32(pf0 - __uint_as_float(ph0));
            const uint32_t pl1 = f2tf32(pf1 - __uint_as_float(ph1));
            const uint32_t pl2 = f2tf32(pf2 - __uint_as_float(ph2));
            const uint32_t pl3 = f2tf32(pf3 - __uint_as_float(ph3));
            #pragma unroll
            for (int nf = 0; nf < 8; ++nf) {
                const int vo = kc * PWK + nf * 8 + g;
                const uint32_t vh0 = VH[vo], vh1 = VH[vo + 4 * PWK];
                const uint32_t vl0 = VL[vo], vl1 = VL[vo + 4 * PWK];
                mma_tf32(oacc[nf], ph0, ph1, ph2, ph3, vh0, vh1);
                mma_tf32(oacc[nf], ph0, ph1, ph2, ph3, vl0, vl1);
                mma_tf32(oacc[nf], pl0, pl1, pl2, pl3, vh0, vh1);
            }
        }

        __syncthreads();                       // everyone done with this buffer
        if (kt + 2 < nkt) ISSUE(kt + 2, kt & 1);
    }

    // ---- finalize: y[b][t][h*64+d] = O / l ----
    const float i0 = __frcp_rn(l0), i1 = __frcp_rn(l1);
    const int rg0 = qbase + wid * 16 + g;
    float* y0 = g_y + (size_t)(b * T_ + rg0) * C_ + h * D_;
    float* y1 = g_y + (size_t)(b * T_ + rg0 + 8) * C_ + h * D_;
    #pragma unroll
    for (int nf = 0; nf < 8; ++nf) {
        *(float2*)&y0[nf * 8 + 2 * tig] = make_float2(oacc[nf][0] * i0, oacc[nf][1] * i0);
        *(float2*)&y1[nf * 8 + 2 * tig] = make_float2(oacc[nf][2] * i1, oacc[nf][3] * i1);
    }
}

// ---------------------------------------------------------------------------
extern "C" void kernel_launch(void* const* d_in, const int* in_sizes, int n_in,
                              void* d_out, int out_size)
{
    const float* x      = (const float*)d_in[0];
    const float* w_attn = (const float*)d_in[1];
    const float* b_attn = (const float*)d_in[2];
    const float* w_proj = (const float*)d_in[3];
    const float* b_proj = (const float*)d_in[4];
    float* out = (float*)d_out;

    const int gemm_smem = 2 * BUF_W * (int)sizeof(uint32_t);   // 73728 B
    cudaFuncSetAttribute(gemm_mma<0>, cudaFuncAttributeMaxDynamicSharedMemorySize, gemm_smem);
    cudaFuncSetAttribute(gemm_mma<1>, cudaFuncAttributeMaxDynamicSharedMemorySize, gemm_smem);
    cudaFuncSetAttribute(attn_mma, cudaFuncAttributeMaxDynamicSharedMemorySize, ATTN_SMEM_BYTES);

    // 1) QKV GEMM (tf32 mma.sync) -> q/k/v tf32 hi/lo planes (q pre-scaled)
    gemm_mma<0><<<dim3(3*C_/128, S_/128), 256, gemm_smem>>>(x, w_attn, b_attn, nullptr, 3*C_, C_);

    // 2) Tensor-core causal flash attention -> g_y [B,T,C]
    attn_mma<<<dim3(T_/BQ, H_, B_), 256, ATTN_SMEM_BYTES>>>();

    // 3) Proj GEMM (tf32 mma.sync) + bias -> out
    gemm_mma<1><<<dim3(C_/128, S_/128), 256, gemm_smem>>>(nullptr, w_proj, b_proj, out, C_, C_);
}

// round 5
// speedup vs baseline: 3.5046x; 1.2285x over previous
#include <cuda_runtime.h>
#include <math_constants.h>
#include <cstdint>

#define B_ 4
#define T_ 2048
#define C_ 1024
#define H_ 16
#define D_ 64
#define S_ (B_*T_)   // 8192

// Scratch (device globals: allocation-free per harness rules)
__device__ uint32_t g_x32[S_*C_];       // x as tf32
__device__ uint32_t g_wa32[C_*3*C_];    // w_attn as tf32
__device__ uint32_t g_wp32[C_*C_];      // w_proj as tf32
__device__ uint32_t g_y32[S_*C_];       // attention output as tf32
// q/k/v tf32 hi/lo planes (3xTF32 split), layout [B,H,T,D]
__device__ uint32_t g_qhi[B_*H_*T_*D_];
__device__ uint32_t g_qlo[B_*H_*T_*D_];
__device__ uint32_t g_khi[B_*H_*T_*D_];
__device__ uint32_t g_klo[B_*H_*T_*D_];
__device__ uint32_t g_vhi[B_*H_*T_*D_];
__device__ uint32_t g_vlo[B_*H_*T_*D_];

__device__ __forceinline__ uint32_t f2tf32(float f) {
    uint32_t r;
    asm("cvt.rna.tf32.f32 %0, %1;" : "=r"(r) : "f"(f));
    return r;
}

// mma.sync m16n8k8 tf32: D += A*B.  A row-major 16x8, B col-major 8x8.
// Frag maps (g=lane>>2, tig=lane&3):
//  A: a0=(g,tig) a1=(g+8,tig) a2=(g,tig+4) a3=(g+8,tig+4)
//  B: b0=(k=tig,n=g) b1=(k=tig+4,n=g)
//  C: c0=(g,2tig) c1=(g,2tig+1) c2=(g+8,2tig) c3=(g+8,2tig+1)
__device__ __forceinline__ void mma_tf32(float c[4],
                                         uint32_t a0, uint32_t a1, uint32_t a2, uint32_t a3,
                                         uint32_t b0, uint32_t b1) {
    asm volatile(
        "mma.sync.aligned.m16n8k8.row.col.f32.tf32.tf32.f32 "
        "{%0,%1,%2,%3}, {%4,%5,%6,%7}, {%8,%9}, {%0,%1,%2,%3};"
        : "+f"(c[0]), "+f"(c[1]), "+f"(c[2]), "+f"(c[3])
        : "r"(a0), "r"(a1), "r"(a2), "r"(a3), "r"(b0), "r"(b1));
}

// ---------------------------------------------------------------------------
// fp32 -> tf32 bulk converter (bandwidth-bound, float4 granularity)
// ---------------------------------------------------------------------------
__global__ __launch_bounds__(256)
void conv_tf32(const float* __restrict__ s, uint32_t* __restrict__ d, int n4)
{
    const int i = blockIdx.x * blockDim.x + threadIdx.x;
    if (i < n4) {
        float4 v = ((const float4*)s)[i];
        uint4 w;
        w.x = f2tf32(v.x); w.y = f2tf32(v.y); w.z = f2tf32(v.z); w.w = f2tf32(v.w);
        ((uint4*)d)[i] = w;
    }
}

// ---------------------------------------------------------------------------
// TF32 tensor-core GEMM (mma.sync), 128x128 CTA tile, 8 warps of 64x32.
// Inputs pre-converted to tf32 -> cp.async 3-stage pipeline, no staging regs.
// A smem [m][k] pad 36 (bank 4g+tig), B smem [k][n] pad 136 (bank 8tig+g).
// MODE 0: epilogue splits qkv into tf32 hi/lo planes (q scaled 1/8).
// MODE 1: epilogue writes fp32 out + bias.
// ---------------------------------------------------------------------------
#define PA 36
#define PB 136
#define AW (128*PA)          // 4608 words
#define BW (32*PB)           // 4352 words
#define STW (AW+BW)          // 8960 words per stage
#define GEMM_SMEM (3*STW*4)  // 107520 B

template<int MODE>
__global__ __launch_bounds__(256, 2)
void gemm_mma(const uint32_t* __restrict__ A32,
              const uint32_t* __restrict__ W32,
              const float* __restrict__ bias,
              float* __restrict__ out,
              int N, int K)
{
    extern __shared__ uint32_t sm4[];
    uint32_t sbase;
    asm("{ .reg .u64 t; cvta.to.shared.u64 t, %1; cvt.u32.u64 %0, t; }"
        : "=r"(sbase) : "l"(sm4));

    const int tid = threadIdx.x;
    const int wid = tid >> 5, lane = tid & 31;
    const int g = lane >> 2, tig = lane & 3;
    const int wm = (wid & 1) * 64;
    const int wn = (wid >> 1) * 32;
    const int bm = blockIdx.y * 128, bn = blockIdx.x * 128;

    float acc[4][4][4];
    #pragma unroll
    for (int i = 0; i < 4; ++i)
        #pragma unroll
        for (int j = 0; j < 4; ++j)
            #pragma unroll
            for (int k = 0; k < 4; ++k) acc[i][j][k] = 0.f;

    const int nch = K / 32;

    auto ISSUE = [&](int c, int st) {
        const int k0 = c * 32;
        const uint32_t so = st * STW;
        #pragma unroll
        for (int i = 0; i < 4; ++i) {              // A: 128 rows x 32 k
            const int idx = tid + i * 256;
            const int row = idx >> 3, kq = idx & 7;
            const uint32_t* src = A32 + (size_t)(bm + row) * K + k0 + kq * 4;
            const uint32_t dst = sbase + (so + row * PA + kq * 4) * 4;
            asm volatile("cp.async.cg.shared.global [%0], [%1], 16;"
                         :: "r"(dst), "l"(src) : "memory");
        }
        #pragma unroll
        for (int i = 0; i < 4; ++i) {              // B: 32 k-rows x 128 n
            const int idx = tid + i * 256;
            const int kr = idx >> 5, n4 = (idx & 31) << 2;
            const uint32_t* src = W32 + (size_t)(k0 + kr) * N + bn + n4;
            const uint32_t dst = sbase + (so + AW + kr * PB + n4) * 4;
            asm volatile("cp.async.cg.shared.global [%0], [%1], 16;"
                         :: "r"(dst), "l"(src) : "memory");
        }
        asm volatile("cp.async.commit_group;" ::: "memory");
    };

    auto COMPUTE = [&](int st) {
        const uint32_t* As = sm4 + st * STW;
        const uint32_t* Bs = As + AW;
        #pragma unroll
        for (int ks = 0; ks < 4; ++ks) {
            uint32_t af[4][4];
            #pragma unroll
            for (int mf = 0; mf < 4; ++mf) {
                const int r0 = wm + mf * 16 + g;
                af[mf][0] = As[r0 * PA + ks * 8 + tig];
                af[mf][1] = As[(r0 + 8) * PA + ks * 8 + tig];
                af[mf][2] = As[r0 * PA + ks * 8 + tig + 4];
                af[mf][3] = As[(r0 + 8) * PA + ks * 8 + tig + 4];
            }
            uint32_t bf[4][2];
            #pragma unroll
            for (int nf = 0; nf < 4; ++nf) {
                const int n0 = wn + nf * 8 + g;
                bf[nf][0] = Bs[(ks * 8 + tig) * PB + n0];
                bf[nf][1] = Bs[(ks * 8 + tig + 4) * PB + n0];
            }
            #pragma unroll
            for (int mf = 0; mf < 4; ++mf)
                #pragma unroll
                for (int nf = 0; nf < 4; ++nf)
                    mma_tf32(acc[mf][nf], af[mf][0], af[mf][1], af[mf][2], af[mf][3],
                             bf[nf][0], bf[nf][1]);
        }
    };

    ISSUE(0, 0);
    ISSUE(1, 1);
    for (int c = 0; c < nch; ++c) {
        if (c + 1 < nch) asm volatile("cp.async.wait_group 1;" ::: "memory");
        else             asm volatile("cp.async.wait_group 0;" ::: "memory");
        __syncthreads();
        COMPUTE(c % 3);
        if (c + 2 < nch) ISSUE(c + 2, (c + 2) % 3);
    }

    #pragma unroll
    for (int mf = 0; mf < 4; ++mf) {
        const int r0 = bm + wm + mf * 16 + g;
        #pragma unroll
        for (int nf = 0; nf < 4; ++nf) {
            const int n0 = bn + wn + nf * 8 + tig * 2;
            const float bv0 = bias[n0], bv1 = bias[n0 + 1];
            float v00 = acc[mf][nf][0] + bv0, v01 = acc[mf][nf][1] + bv1;
            float v10 = acc[mf][nf][2] + bv0, v11 = acc[mf][nf][3] + bv1;
            if (MODE == 0) {
                const int part = n0 >> 10;               // 0:q 1:k 2:v
                const int cl = n0 & 1023;
                const int hh = cl >> 6, dd = cl & 63;
                uint32_t *dh, *dl;
                if (part == 0) { dh = g_qhi; dl = g_qlo; v00 *= 0.125f; v01 *= 0.125f; v10 *= 0.125f; v11 *= 0.125f; }
                else if (part == 1) { dh = g_khi; dl = g_klo; }
                else { dh = g_vhi; dl = g_vlo; }
                const uint32_t h00 = f2tf32(v00), h01 = f2tf32(v01);
                const uint32_t h10 = f2tf32(v10), h11 = f2tf32(v11);
                const uint32_t l00 = f2tf32(v00 - __uint_as_float(h00));
                const uint32_t l01 = f2tf32(v01 - __uint_as_float(h01));
                const uint32_t l10 = f2tf32(v10 - __uint_as_float(h10));
                const uint32_t l11 = f2tf32(v11 - __uint_as_float(h11));
                const int bb0 = r0 >> 11, tt0 = r0 & 2047;
                const int r1 = r0 + 8;
                const int bb1 = r1 >> 11, tt1 = r1 & 2047;
                const int i0 = ((((bb0 * H_ + hh) * T_) + tt0) << 6) + dd;
                const int i1 = ((((bb1 * H_ + hh) * T_) + tt1) << 6) + dd;
                *(uint2*)&dh[i0] = make_uint2(h00, h01);
                *(uint2*)&dl[i0] = make_uint2(l00, l01);
                *(uint2*)&dh[i1] = make_uint2(h10, h11);
                *(uint2*)&dl[i1] = make_uint2(l10, l11);
            } else {
                *(float2*)&out[(size_t)r0 * N + n0]       = make_float2(v00, v01);
                *(float2*)&out[(size_t)(r0 + 8) * N + n0] = make_float2(v10, v11);
            }
        }
    }
}

// ---------------------------------------------------------------------------
// Tensor-core causal flash attention (mma.sync tf32, 3xTF32 both products).
// CTA: 128 q-rows for one (b,h). 8 warps x 16 rows. K/V tiles of 64 rows,
// cp.async double-buffered. Per-plane smem strides chosen conflict-free:
// K planes pad 68 (bank 4g+tig for K-frag reads), V planes pad 72 (bank
// 8tig+g for V-frag reads), P pad 68 (bank 4g+tig for P-frag reads).
// ---------------------------------------------------------------------------
#define BQ 128
#define PWK 68
#define PWV 72
#define PWP 68
#define KPW (64*PWK)            // 4352 words / K plane
#define VPW (64*PWV)            // 4608 words / V plane
#define BUFW (2*KPW + 2*VPW)    // 17920 words / buffer
#define PS_OFF (2*BUFW)         // 35840
#define ATTN_SMEM_BYTES ((PS_OFF + BQ*PWP)*4)   // 178176 B

__global__ __launch_bounds__(256, 1)
void attn_mma()
{
    extern __shared__ uint32_t sw[];
    uint32_t sbase;
    asm("{ .reg .u64 t; cvta.to.shared.u64 t, %1; cvt.u32.u64 %0, t; }"
        : "=r"(sbase) : "l"(sw));

    const int tid = threadIdx.x, wid = tid >> 5, lane = tid & 31;
    const int g = lane >> 2, tig = lane & 3;
    const int qt = blockIdx.x, h = blockIdx.y, b = blockIdx.z;
    const int qbase = qt * BQ;
    const size_t pb = (size_t)((b * H_ + h) * T_) * D_;

    // Q fragments (hi/lo), register-resident: rows qbase+wid*16+{g,g+8}
    uint32_t aqh[8][4], aql[8][4];
    {
        const uint32_t* qh = g_qhi + pb;
        const uint32_t* ql = g_qlo + pb;
        const int r0 = qbase + wid * 16 + g;
        #pragma unroll
        for (int ks = 0; ks < 8; ++ks) {
            const int c = ks * 8 + tig;
            aqh[ks][0] = qh[(size_t)r0 * 64 + c];
            aqh[ks][1] = qh[(size_t)(r0 + 8) * 64 + c];
            aqh[ks][2] = qh[(size_t)r0 * 64 + c + 4];
            aqh[ks][3] = qh[(size_t)(r0 + 8) * 64 + c + 4];
            aql[ks][0] = ql[(size_t)r0 * 64 + c];
            aql[ks][1] = ql[(size_t)(r0 + 8) * 64 + c];
            aql[ks][2] = ql[(size_t)r0 * 64 + c + 4];
            aql[ks][3] = ql[(size_t)(r0 + 8) * 64 + c + 4];
        }
    }

    float oacc[8][4];
    #pragma unroll
    for (int nf = 0; nf < 8; ++nf)
        #pragma unroll
        for (int j = 0; j < 4; ++j) oacc[nf][j] = 0.f;
    float m0 = -CUDART_INF_F, m1 = -CUDART_INF_F, l0 = 0.f, l1 = 0.f;

    const int nkt = 2 * qt + 2;

    auto ISSUE = [&](int kt, int buf) {
        const uint32_t bufo = buf * BUFW;
        #pragma unroll
        for (int p = 0; p < 4; ++p) {
            const uint32_t* plane =
                (p == 0) ? g_khi : (p == 1) ? g_klo : (p == 2) ? g_vhi : g_vlo;
            const uint32_t pofs = (p == 0) ? 0u : (p == 1) ? (uint32_t)KPW
                                : (p == 2) ? (uint32_t)(2 * KPW) : (uint32_t)(2 * KPW + VPW);
            const int str = (p < 2) ? PWK : PWV;
            #pragma unroll
            for (int i = 0; i < 4; ++i) {
                const int idx = tid + i * 256;
                const int row = idx >> 4, c4 = (idx & 15) << 2;
                const uint32_t* src = plane + pb + (size_t)(kt * 64 + row) * 64 + c4;
                const uint32_t dst = sbase + (bufo + pofs + row * str + c4) * 4;
                asm volatile("cp.async.cg.shared.global [%0], [%1], 16;"
                             :: "r"(dst), "l"(src) : "memory");
            }
        }
        asm volatile("cp.async.commit_group;" ::: "memory");
    };

    ISSUE(0, 0);
    if (nkt > 1) ISSUE(1, 1);

    for (int kt = 0; kt < nkt; ++kt) {
        if (kt < nkt - 1) asm volatile("cp.async.wait_group 1;" ::: "memory");
        else              asm volatile("cp.async.wait_group 0;" ::: "memory");
        __syncthreads();

        const uint32_t* KH = sw + (kt & 1) * BUFW;
        const uint32_t* KL = KH + KPW;
        const uint32_t* VH = KH + 2 * KPW;
        const uint32_t* VL = VH + VPW;
        float* Ps = (float*)(sw + PS_OFF);

        // ---- S = Q K^T (3xTF32) ----
        float sa[8][4];
        #pragma unroll
        for (int nf = 0; nf < 8; ++nf)
            #pragma unroll
            for (int j = 0; j < 4; ++j) sa[nf][j] = 0.f;
        #pragma unroll
        for (int ks = 0; ks < 8; ++ks) {
            #pragma unroll
            for (int nf = 0; nf < 8; ++nf) {
                const int bo = (nf * 8 + g) * PWK + ks * 8 + tig;
                const uint32_t bh0 = KH[bo], bh1 = KH[bo + 4];
                const uint32_t bl0 = KL[bo], bl1 = KL[bo + 4];
                mma_tf32(sa[nf], aqh[ks][0], aqh[ks][1], aqh[ks][2], aqh[ks][3], bh0, bh1);
                mma_tf32(sa[nf], aqh[ks][0], aqh[ks][1], aqh[ks][2], aqh[ks][3], bl0, bl1);
                mma_tf32(sa[nf], aql[ks][0], aql[ks][1], aql[ks][2], aql[ks][3], bh0, bh1);
            }
        }

        // ---- causal mask ----
        const int ktb = kt * 64;
        const int rg0 = qbase + wid * 16 + g, rg1 = rg0 + 8;
        if (ktb >= qbase) {
            #pragma unroll
            for (int nf = 0; nf < 8; ++nf) {
                const int c0 = ktb + nf * 8 + 2 * tig;
                if (c0     > rg0) sa[nf][0] = -CUDART_INF_F;
                if (c0 + 1 > rg0) sa[nf][1] = -CUDART_INF_F;
                if (c0     > rg1) sa[nf][2] = -CUDART_INF_F;
                if (c0 + 1 > rg1) sa[nf][3] = -CUDART_INF_F;
            }
        }

        // ---- running softmax ----
        float mt0 = -CUDART_INF_F, mt1 = -CUDART_INF_F;
        #pragma unroll
        for (int nf = 0; nf < 8; ++nf) {
            mt0 = fmaxf(mt0, fmaxf(sa[nf][0], sa[nf][1]));
            mt1 = fmaxf(mt1, fmaxf(sa[nf][2], sa[nf][3]));
        }
        mt0 = fmaxf(mt0, __shfl_xor_sync(0xffffffffu, mt0, 1));
        mt0 = fmaxf(mt0, __shfl_xor_sync(0xffffffffu, mt0, 2));
        mt1 = fmaxf(mt1, __shfl_xor_sync(0xffffffffu, mt1, 1));
        mt1 = fmaxf(mt1, __shfl_xor_sync(0xffffffffu, mt1, 2));
        const float mn0 = fmaxf(m0, mt0), mn1 = fmaxf(m1, mt1);
        const float al0 = __expf(m0 - mn0), al1 = __expf(m1 - mn1);
        float ls0 = 0.f, ls1 = 0.f;
        const int prow = wid * 16 + g;
        #pragma unroll
        for (int nf = 0; nf < 8; ++nf) {
            const float p0 = __expf(sa[nf][0] - mn0), p1 = __expf(sa[nf][1] - mn0);
            const float p2 = __expf(sa[nf][2] - mn1), p3 = __expf(sa[nf][3] - mn1);
            ls0 += p0 + p1; ls1 += p2 + p3;
            *(float2*)&Ps[prow * PWP + nf * 8 + 2 * tig]       = make_float2(p0, p1);
            *(float2*)&Ps[(prow + 8) * PWP + nf * 8 + 2 * tig] = make_float2(p2, p3);
        }
        ls0 += __shfl_xor_sync(0xffffffffu, ls0, 1);
        ls0 += __shfl_xor_sync(0xffffffffu, ls0, 2);
        ls1 += __shfl_xor_sync(0xffffffffu, ls1, 1);
        ls1 += __shfl_xor_sync(0xffffffffu, ls1, 2);
        l0 = l0 * al0 + ls0;
        l1 = l1 * al1 + ls1;
        m0 = mn0; m1 = mn1;
        #pragma unroll
        for (int nf = 0; nf < 8; ++nf) {
            oacc[nf][0] *= al0; oacc[nf][1] *= al0;
            oacc[nf][2] *= al1; oacc[nf][3] *= al1;
        }
        __syncwarp();   // P rows are warp-private

        // ---- O += P V (3xTF32; P hi/lo split in registers) ----
        #pragma unroll
        for (int ks = 0; ks < 8; ++ks) {
            const int kc = ks * 8 + tig;
            const float pf0 = Ps[prow * PWP + kc];
            const float pf1 = Ps[(prow + 8) * PWP + kc];
            const float pf2 = Ps[prow * PWP + kc + 4];
            const float pf3 = Ps[(prow + 8) * PWP + kc + 4];
            const uint32_t ph0 = f2tf32(pf0), ph1 = f2tf32(pf1);
            const uint32_t ph2 = f2tf32(pf2), ph3 = f2tf32(pf3);
            const uint32_t pl0 = f2tf32(pf0 - __uint_as_float(ph0));
            const uint32_t pl1 = f2tf32(pf1 - __uint_as_float(ph1));
            const uint32_t pl2 = f2tf32(pf2 - __uint_as_float(ph2));
            const uint32_t pl3 = f2tf32(pf3 - __uint_as_float(ph3));
            #pragma unroll
            for (int nf = 0; nf < 8; ++nf) {
                const int vo = kc * PWV + nf * 8 + g;
                const uint32_t vh0 = VH[vo], vh1 = VH[vo + 4 * PWV];
                const uint32_t vl0 = VL[vo], vl1 = VL[vo + 4 * PWV];
                mma_tf32(oacc[nf], ph0, ph1, ph2, ph3, vh0, vh1);
                mma_tf32(oacc[nf], ph0, ph1, ph2, ph3, vl0, vl1);
                mma_tf32(oacc[nf], pl0, pl1, pl2, pl3, vh0, vh1);
            }
        }

        __syncthreads();
        if (kt + 2 < nkt) ISSUE(kt + 2, kt & 1);
    }

    // ---- finalize: y (tf32) for the proj GEMM ----
    const float i0 = __frcp_rn(l0), i1 = __frcp_rn(l1);
    const int rg0 = qbase + wid * 16 + g;
    uint32_t* y0 = g_y32 + (size_t)(b * T_ + rg0) * C_ + h * D_;
    uint32_t* y1 = g_y32 + (size_t)(b * T_ + rg0 + 8) * C_ + h * D_;
    #pragma unroll
    for (int nf = 0; nf < 8; ++nf) {
        *(uint2*)&y0[nf * 8 + 2 * tig] =
            make_uint2(f2tf32(oacc[nf][0] * i0), f2tf32(oacc[nf][1] * i0));
        *(uint2*)&y1[nf * 8 + 2 * tig] =
            make_uint2(f2tf32(oacc[nf][2] * i1), f2tf32(oacc[nf][3] * i1));
    }
}

// ---------------------------------------------------------------------------
extern "C" void kernel_launch(void* const* d_in, const int* in_sizes, int n_in,
                              void* d_out, int out_size)
{
    const float* x      = (const float*)d_in[0];
    const float* w_attn = (const float*)d_in[1];
    const float* b_attn = (const float*)d_in[2];
    const float* w_proj = (const float*)d_in[3];
    const float* b_proj = (const float*)d_in[4];
    float* out = (float*)d_out;

    cudaFuncSetAttribute(gemm_mma<0>, cudaFuncAttributeMaxDynamicSharedMemorySize, GEMM_SMEM);
    cudaFuncSetAttribute(gemm_mma<1>, cudaFuncAttributeMaxDynamicSharedMemorySize, GEMM_SMEM);
    cudaFuncSetAttribute(attn_mma, cudaFuncAttributeMaxDynamicSharedMemorySize, ATTN_SMEM_BYTES);

    // 0) pre-convert inputs to tf32 (bandwidth pass; enables cp.async GEMM)
    uint32_t* px; cudaGetSymbolAddress((void**)&px, g_x32);
    uint32_t* pa; cudaGetSymbolAddress((void**)&pa, g_wa32);
    uint32_t* pp; cudaGetSymbolAddress((void**)&pp, g_wp32);
    uint32_t* py; cudaGetSymbolAddress((void**)&py, g_y32);
    conv_tf32<<<(S_*C_/4 + 255)/256, 256>>>(x, px, S_*C_/4);
    conv_tf32<<<(C_*3*C_/4 + 255)/256, 256>>>(w_attn, pa, C_*3*C_/4);
    conv_tf32<<<(C_*C_/4 + 255)/256, 256>>>(w_proj, pp, C_*C_/4);

    // 1) QKV GEMM -> q/k/v tf32 hi/lo planes (q pre-scaled by 1/8)
    gemm_mma<0><<<dim3(3*C_/128, S_/128), 256, GEMM_SMEM>>>(px, pa, b_attn, nullptr, 3*C_, C_);

    // 2) Tensor-core causal flash attention -> g_y32 (tf32)
    attn_mma<<<dim3(T_/BQ, H_, B_), 256, ATTN_SMEM_BYTES>>>();

    // 3) Proj GEMM + bias -> out (fp32)
    gemm_mma<1><<<dim3(C_/128, S_/128), 256, GEMM_SMEM>>>(py, pp, b_proj, out, C_, C_);
}

// round 6
// speedup vs baseline: 3.7231x; 1.0623x over previous
#include <cuda_runtime.h>
#include <math_constants.h>
#include <cstdint>

#define B_ 4
#define T_ 2048
#define C_ 1024
#define H_ 16
#define D_ 64
#define S_ (B_*T_)   // 8192

// Scratch (device globals: allocation-free per harness rules)
__device__ uint32_t g_x32[S_*C_];       // x as tf32
__device__ uint32_t g_wa32[C_*3*C_];    // w_attn as tf32
__device__ uint32_t g_wp32[C_*C_];      // w_proj as tf32
__device__ uint32_t g_y32[S_*C_];       // attention output as tf32
// q/v tf32 hi/lo planes, k hi only (k_lo dropped: QK = (q_hi+q_lo)·k_hi)
__device__ uint32_t g_qhi[B_*H_*T_*D_];
__device__ uint32_t g_qlo[B_*H_*T_*D_];
__device__ uint32_t g_khi[B_*H_*T_*D_];
__device__ uint32_t g_vhi[B_*H_*T_*D_];
__device__ uint32_t g_vlo[B_*H_*T_*D_];

__device__ __forceinline__ uint32_t f2tf32(float f) {
    uint32_t r;
    asm("cvt.rna.tf32.f32 %0, %1;" : "=r"(r) : "f"(f));
    return r;
}

// mma.sync m16n8k8 tf32: D += A*B.  A row-major 16x8, B col-major 8x8.
// Frag maps (g=lane>>2, tig=lane&3):
//  A: a0=(g,tig) a1=(g+8,tig) a2=(g,tig+4) a3=(g+8,tig+4)
//  B: b0=(k=tig,n=g) b1=(k=tig+4,n=g)
//  C: c0=(g,2tig) c1=(g,2tig+1) c2=(g+8,2tig) c3=(g+8,2tig+1)
__device__ __forceinline__ void mma_tf32(float c[4],
                                         uint32_t a0, uint32_t a1, uint32_t a2, uint32_t a3,
                                         uint32_t b0, uint32_t b1) {
    asm volatile(
        "mma.sync.aligned.m16n8k8.row.col.f32.tf32.tf32.f32 "
        "{%0,%1,%2,%3}, {%4,%5,%6,%7}, {%8,%9}, {%0,%1,%2,%3};"
        : "+f"(c[0]), "+f"(c[1]), "+f"(c[2]), "+f"(c[3])
        : "r"(a0), "r"(a1), "r"(a2), "r"(a3), "r"(b0), "r"(b1));
}

// ---------------------------------------------------------------------------
// fp32 -> tf32 bulk converter
// ---------------------------------------------------------------------------
__global__ __launch_bounds__(256)
void conv_tf32(const float* __restrict__ s, uint32_t* __restrict__ d, int n4)
{
    const int i = blockIdx.x * blockDim.x + threadIdx.x;
    if (i < n4) {
        float4 v = ((const float4*)s)[i];
        uint4 w;
        w.x = f2tf32(v.x); w.y = f2tf32(v.y); w.z = f2tf32(v.z); w.w = f2tf32(v.w);
        ((uint4*)d)[i] = w;
    }
}

// ---------------------------------------------------------------------------
// TF32 tensor-core GEMM: 256x128 CTA tile, 512 threads (16 warps of 64x32),
// cp.async 3-stage pipeline. A smem [m][k] pad 36, B smem [k][n] pad 136.
// MODE 0: epilogue -> q hi/lo, k hi, v hi/lo planes (q pre-scaled by 1/8).
// MODE 1: epilogue -> fp32 out + bias.
// ---------------------------------------------------------------------------
#define PA 36
#define PB 136
#define AW (256*PA)          // 9216 words
#define BW (32*PB)           // 4352 words
#define STW (AW+BW)          // 13568 words per stage
#define GEMM_SMEM (3*STW*4)  // 162816 B

template<int MODE>
__global__ __launch_bounds__(512, 1)
void gemm_mma(const uint32_t* __restrict__ A32,
              const uint32_t* __restrict__ W32,
              const float* __restrict__ bias,
              float* __restrict__ out,
              int N, int K)
{
    extern __shared__ uint32_t sm4[];
    uint32_t sbase;
    asm("{ .reg .u64 t; cvta.to.shared.u64 t, %1; cvt.u32.u64 %0, t; }"
        : "=r"(sbase) : "l"(sm4));

    const int tid = threadIdx.x;
    const int wid = tid >> 5, lane = tid & 31;
    const int g = lane >> 2, tig = lane & 3;
    const int wm = (wid & 3) * 64;       // 0,64,128,192
    const int wn = (wid >> 2) * 32;      // 0,32,64,96
    const int bm = blockIdx.y * 256, bn = blockIdx.x * 128;

    float acc[4][4][4];
    #pragma unroll
    for (int i = 0; i < 4; ++i)
        #pragma unroll
        for (int j = 0; j < 4; ++j)
            #pragma unroll
            for (int k = 0; k < 4; ++k) acc[i][j][k] = 0.f;

    const int nch = K / 32;

    auto ISSUE = [&](int c, int st) {
        const int k0 = c * 32;
        const uint32_t so = st * STW;
        #pragma unroll
        for (int i = 0; i < 4; ++i) {              // A: 256 rows x 32 k
            const int idx = tid + i * 512;
            const int row = idx >> 3, kq = idx & 7;
            const uint32_t* src = A32 + (size_t)(bm + row) * K + k0 + kq * 4;
            const uint32_t dst = sbase + (so + row * PA + kq * 4) * 4;
            asm volatile("cp.async.cg.shared.global [%0], [%1], 16;"
                         :: "r"(dst), "l"(src) : "memory");
        }
        #pragma unroll
        for (int i = 0; i < 2; ++i) {              // B: 32 k-rows x 128 n
            const int idx = tid + i * 512;
            const int kr = idx >> 5, n4 = (idx & 31) << 2;
            const uint32_t* src = W32 + (size_t)(k0 + kr) * N + bn + n4;
            const uint32_t dst = sbase + (so + AW + kr * PB + n4) * 4;
            asm volatile("cp.async.cg.shared.global [%0], [%1], 16;"
                         :: "r"(dst), "l"(src) : "memory");
        }
        asm volatile("cp.async.commit_group;" ::: "memory");
    };

    auto COMPUTE = [&](int st) {
        const uint32_t* As = sm4 + st * STW;
        const uint32_t* Bs = As + AW;
        #pragma unroll
        for (int ks = 0; ks < 4; ++ks) {
            uint32_t af[4][4];
            #pragma unroll
            for (int mf = 0; mf < 4; ++mf) {
                const int r0 = wm + mf * 16 + g;
                af[mf][0] = As[r0 * PA + ks * 8 + tig];
                af[mf][1] = As[(r0 + 8) * PA + ks * 8 + tig];
                af[mf][2] = As[r0 * PA + ks * 8 + tig + 4];
                af[mf][3] = As[(r0 + 8) * PA + ks * 8 + tig + 4];
            }
            uint32_t bf[4][2];
            #pragma unroll
            for (int nf = 0; nf < 4; ++nf) {
                const int n0 = wn + nf * 8 + g;
                bf[nf][0] = Bs[(ks * 8 + tig) * PB + n0];
                bf[nf][1] = Bs[(ks * 8 + tig + 4) * PB + n0];
            }
            #pragma unroll
            for (int mf = 0; mf < 4; ++mf)
                #pragma unroll
                for (int nf = 0; nf < 4; ++nf)
                    mma_tf32(acc[mf][nf], af[mf][0], af[mf][1], af[mf][2], af[mf][3],
                             bf[nf][0], bf[nf][1]);
        }
    };

    ISSUE(0, 0);
    ISSUE(1, 1);
    for (int c = 0; c < nch; ++c) {
        if (c + 1 < nch) asm volatile("cp.async.wait_group 1;" ::: "memory");
        else             asm volatile("cp.async.wait_group 0;" ::: "memory");
        __syncthreads();
        COMPUTE(c % 3);
        if (c + 2 < nch) ISSUE(c + 2, (c + 2) % 3);
    }

    #pragma unroll
    for (int mf = 0; mf < 4; ++mf) {
        const int r0 = bm + wm + mf * 16 + g;
        #pragma unroll
        for (int nf = 0; nf < 4; ++nf) {
            const int n0 = bn + wn + nf * 8 + tig * 2;
            const float bv0 = bias[n0], bv1 = bias[n0 + 1];
            float v00 = acc[mf][nf][0] + bv0, v01 = acc[mf][nf][1] + bv1;
            float v10 = acc[mf][nf][2] + bv0, v11 = acc[mf][nf][3] + bv1;
            if (MODE == 0) {
                const int part = n0 >> 10;               // 0:q 1:k 2:v
                const int cl = n0 & 1023;
                const int hh = cl >> 6, dd = cl & 63;
                const int bb0 = r0 >> 11, tt0 = r0 & 2047;
                const int r1 = r0 + 8;
                const int bb1 = r1 >> 11, tt1 = r1 & 2047;
                const int i0 = ((((bb0 * H_ + hh) * T_) + tt0) << 6) + dd;
                const int i1 = ((((bb1 * H_ + hh) * T_) + tt1) << 6) + dd;
                if (part == 0) {
                    v00 *= 0.125f; v01 *= 0.125f; v10 *= 0.125f; v11 *= 0.125f;
                    const uint32_t h00 = f2tf32(v00), h01 = f2tf32(v01);
                    const uint32_t h10 = f2tf32(v10), h11 = f2tf32(v11);
                    *(uint2*)&g_qhi[i0] = make_uint2(h00, h01);
                    *(uint2*)&g_qhi[i1] = make_uint2(h10, h11);
                    *(uint2*)&g_qlo[i0] = make_uint2(f2tf32(v00 - __uint_as_float(h00)),
                                                     f2tf32(v01 - __uint_as_float(h01)));
                    *(uint2*)&g_qlo[i1] = make_uint2(f2tf32(v10 - __uint_as_float(h10)),
                                                     f2tf32(v11 - __uint_as_float(h11)));
                } else if (part == 1) {
                    *(uint2*)&g_khi[i0] = make_uint2(f2tf32(v00), f2tf32(v01));
                    *(uint2*)&g_khi[i1] = make_uint2(f2tf32(v10), f2tf32(v11));
                } else {
                    const uint32_t h00 = f2tf32(v00), h01 = f2tf32(v01);
                    const uint32_t h10 = f2tf32(v10), h11 = f2tf32(v11);
                    *(uint2*)&g_vhi[i0] = make_uint2(h00, h01);
                    *(uint2*)&g_vhi[i1] = make_uint2(h10, h11);
                    *(uint2*)&g_vlo[i0] = make_uint2(f2tf32(v00 - __uint_as_float(h00)),
                                                     f2tf32(v01 - __uint_as_float(h01)));
                    *(uint2*)&g_vlo[i1] = make_uint2(f2tf32(v10 - __uint_as_float(h10)),
                                                     f2tf32(v11 - __uint_as_float(h11)));
                }
            } else {
                *(float2*)&out[(size_t)r0 * N + n0]       = make_float2(v00, v01);
                *(float2*)&out[(size_t)(r0 + 8) * N + n0] = make_float2(v10, v11);
            }
        }
    }
}

// ---------------------------------------------------------------------------
// Tensor-core causal flash attention.
// QK: 2-term ((q_hi+q_lo)*k_hi); PV: 3-term 3xTF32. K/V tiles of 64 rows,
// 3 planes (khi,vhi,vlo), cp.async double-buffered. Conflict-free strides:
// K plane 68 (bank 4g+tig), V planes 72 (bank 8tig+g), P 68.
// Big q-tiles launch first (qt reversed) for wave balance.
// ---------------------------------------------------------------------------
#define BQ 128
#define PWK 68
#define PWV 72
#define PWP 68
#define KPW (64*PWK)            // 4352 words (k_hi plane)
#define VPW (64*PWV)            // 4608 words per V plane
#define BUFW (KPW + 2*VPW)      // 13568 words per buffer
#define PS_OFF (2*BUFW)         // 27136
#define ATTN_SMEM_BYTES ((PS_OFF + BQ*PWP)*4)   // 143360 B

__global__ __launch_bounds__(256, 1)
void attn_mma()
{
    extern __shared__ uint32_t sw[];
    uint32_t sbase;
    asm("{ .reg .u64 t; cvta.to.shared.u64 t, %1; cvt.u32.u64 %0, t; }"
        : "=r"(sbase) : "l"(sw));

    const int tid = threadIdx.x, wid = tid >> 5, lane = tid & 31;
    const int g = lane >> 2, tig = lane & 3;
    const int qt = gridDim.x - 1 - blockIdx.x;   // big tiles first
    const int h = blockIdx.y, b = blockIdx.z;
    const int qbase = qt * BQ;
    const size_t pb = (size_t)((b * H_ + h) * T_) * D_;

    // Q fragments (hi/lo), register-resident: rows qbase+wid*16+{g,g+8}
    uint32_t aqh[8][4], aql[8][4];
    {
        const uint32_t* qh = g_qhi + pb;
        const uint32_t* ql = g_qlo + pb;
        const int r0 = qbase + wid * 16 + g;
        #pragma unroll
        for (int ks = 0; ks < 8; ++ks) {
            const int c = ks * 8 + tig;
            aqh[ks][0] = qh[(size_t)r0 * 64 + c];
            aqh[ks][1] = qh[(size_t)(r0 + 8) * 64 + c];
            aqh[ks][2] = qh[(size_t)r0 * 64 + c + 4];
            aqh[ks][3] = qh[(size_t)(r0 + 8) * 64 + c + 4];
            aql[ks][0] = ql[(size_t)r0 * 64 + c];
            aql[ks][1] = ql[(size_t)(r0 + 8) * 64 + c];
            aql[ks][2] = ql[(size_t)r0 * 64 + c + 4];
            aql[ks][3] = ql[(size_t)(r0 + 8) * 64 + c + 4];
        }
    }

    float oacc[8][4];
    #pragma unroll
    for (int nf = 0; nf < 8; ++nf)
        #pragma unroll
        for (int j = 0; j < 4; ++j) oacc[nf][j] = 0.f;
    float m0 = -CUDART_INF_F, m1 = -CUDART_INF_F, l0 = 0.f, l1 = 0.f;

    const int nkt = 2 * qt + 2;

    auto ISSUE = [&](int kt, int buf) {
        const uint32_t bufo = buf * BUFW;
        #pragma unroll
        for (int p = 0; p < 3; ++p) {
            const uint32_t* plane = (p == 0) ? g_khi : (p == 1) ? g_vhi : g_vlo;
            const uint32_t pofs = (p == 0) ? 0u : (p == 1) ? (uint32_t)KPW
                                                           : (uint32_t)(KPW + VPW);
            const int str = (p == 0) ? PWK : PWV;
            #pragma unroll
            for (int i = 0; i < 4; ++i) {
                const int idx = tid + i * 256;
                const int row = idx >> 4, c4 = (idx & 15) << 2;
                const uint32_t* src = plane + pb + (size_t)(kt * 64 + row) * 64 + c4;
                const uint32_t dst = sbase + (bufo + pofs + row * str + c4) * 4;
                asm volatile("cp.async.cg.shared.global [%0], [%1], 16;"
                             :: "r"(dst), "l"(src) : "memory");
            }
        }
        asm volatile("cp.async.commit_group;" ::: "memory");
    };

    ISSUE(0, 0);
    if (nkt > 1) ISSUE(1, 1);

    for (int kt = 0; kt < nkt; ++kt) {
        if (kt < nkt - 1) asm volatile("cp.async.wait_group 1;" ::: "memory");
        else              asm volatile("cp.async.wait_group 0;" ::: "memory");
        __syncthreads();

        const uint32_t* KH = sw + (kt & 1) * BUFW;
        const uint32_t* VH = KH + KPW;
        const uint32_t* VL = VH + VPW;
        float* Ps = (float*)(sw + PS_OFF);

        // ---- S = Q K^T:  (q_hi + q_lo) * k_hi ----
        float sa[8][4];
        #pragma unroll
        for (int nf = 0; nf < 8; ++nf)
            #pragma unroll
            for (int j = 0; j < 4; ++j) sa[nf][j] = 0.f;
        #pragma unroll
        for (int ks = 0; ks < 8; ++ks) {
            #pragma unroll
            for (int nf = 0; nf < 8; ++nf) {
                const int bo = (nf * 8 + g) * PWK + ks * 8 + tig;
                const uint32_t bh0 = KH[bo], bh1 = KH[bo + 4];
                mma_tf32(sa[nf], aqh[ks][0], aqh[ks][1], aqh[ks][2], aqh[ks][3], bh0, bh1);
                mma_tf32(sa[nf], aql[ks][0], aql[ks][1], aql[ks][2], aql[ks][3], bh0, bh1);
            }
        }

        // ---- causal mask ----
        const int ktb = kt * 64;
        const int rg0 = qbase + wid * 16 + g, rg1 = rg0 + 8;
        if (ktb >= qbase) {
            #pragma unroll
            for (int nf = 0; nf < 8; ++nf) {
                const int c0 = ktb + nf * 8 + 2 * tig;
                if (c0     > rg0) sa[nf][0] = -CUDART_INF_F;
                if (c0 + 1 > rg0) sa[nf][1] = -CUDART_INF_F;
                if (c0     > rg1) sa[nf][2] = -CUDART_INF_F;
                if (c0 + 1 > rg1) sa[nf][3] = -CUDART_INF_F;
            }
        }

        // ---- running softmax ----
        float mt0 = -CUDART_INF_F, mt1 = -CUDART_INF_F;
        #pragma unroll
        for (int nf = 0; nf < 8; ++nf) {
            mt0 = fmaxf(mt0, fmaxf(sa[nf][0], sa[nf][1]));
            mt1 = fmaxf(mt1, fmaxf(sa[nf][2], sa[nf][3]));
        }
        mt0 = fmaxf(mt0, __shfl_xor_sync(0xffffffffu, mt0, 1));
        mt0 = fmaxf(mt0, __shfl_xor_sync(0xffffffffu, mt0, 2));
        mt1 = fmaxf(mt1, __shfl_xor_sync(0xffffffffu, mt1, 1));
        mt1 = fmaxf(mt1, __shfl_xor_sync(0xffffffffu, mt1, 2));
        const float mn0 = fmaxf(m0, mt0), mn1 = fmaxf(m1, mt1);
        const float al0 = __expf(m0 - mn0), al1 = __expf(m1 - mn1);
        float ls0 = 0.f, ls1 = 0.f;
        const int prow = wid * 16 + g;
        #pragma unroll
        for (int nf = 0; nf < 8; ++nf) {
            const float p0 = __expf(sa[nf][0] - mn0), p1 = __expf(sa[nf][1] - mn0);
            const float p2 = __expf(sa[nf][2] - mn1), p3 = __expf(sa[nf][3] - mn1);
            ls0 += p0 + p1; ls1 += p2 + p3;
            *(float2*)&Ps[prow * PWP + nf * 8 + 2 * tig]       = make_float2(p0, p1);
            *(float2*)&Ps[(prow + 8) * PWP + nf * 8 + 2 * tig] = make_float2(p2, p3);
        }
        ls0 += __shfl_xor_sync(0xffffffffu, ls0, 1);
        ls0 += __shfl_xor_sync(0xffffffffu, ls0, 2);
        ls1 += __shfl_xor_sync(0xffffffffu, ls1, 1);
        ls1 += __shfl_xor_sync(0xffffffffu, ls1, 2);
        l0 = l0 * al0 + ls0;
        l1 = l1 * al1 + ls1;
        m0 = mn0; m1 = mn1;
        #pragma unroll
        for (int nf = 0; nf < 8; ++nf) {
            oacc[nf][0] *= al0; oacc[nf][1] *= al0;
            oacc[nf][2] *= al1; oacc[nf][3] *= al1;
        }
        __syncwarp();   // P rows are warp-private

        // ---- O += P V (3xTF32; P hi/lo split in registers) ----
        #pragma unroll
        for (int ks = 0; ks < 8; ++ks) {
            const int kc = ks * 8 + tig;
            const float pf0 = Ps[prow * PWP + kc];
            const float pf1 = Ps[(prow + 8) * PWP + kc];
            const float pf2 = Ps[prow * PWP + kc + 4];
            const float pf3 = Ps[(prow + 8) * PWP + kc + 4];
            const uint32_t ph0 = f2tf32(pf0), ph1 = f2tf32(pf1);
            const uint32_t ph2 = f2tf32(pf2), ph3 = f2tf32(pf3);
            const uint32_t pl0 = f2tf32(pf0 - __uint_as_float(ph0));
            const uint32_t pl1 = f2tf32(pf1 - __uint_as_float(ph1));
            const uint32_t pl2 = f2tf32(pf2 - __uint_as_float(ph2));
            const uint32_t pl3 = f2tf32(pf3 - __uint_as_float(ph3));
            #pragma unroll
            for (int nf = 0; nf < 8; ++nf) {
                const int vo = kc * PWV + nf * 8 + g;
                const uint32_t vh0 = VH[vo], vh1 = VH[vo + 4 * PWV];
                const uint32_t vl0 = VL[vo], vl1 = VL[vo + 4 * PWV];
                mma_tf32(oacc[nf], ph0, ph1, ph2, ph3, vh0, vh1);
                mma_tf32(oacc[nf], ph0, ph1, ph2, ph3, vl0, vl1);
                mma_tf32(oacc[nf], pl0, pl1, pl2, pl3, vh0, vh1);
            }
        }

        __syncthreads();
        if (kt + 2 < nkt) ISSUE(kt + 2, kt & 1);
    }

    // ---- finalize: y (tf32) for the proj GEMM ----
    const float i0 = __frcp_rn(l0), i1 = __frcp_rn(l1);
    const int rg0 = qbase + wid * 16 + g;
    uint32_t* y0 = g_y32 + (size_t)(b * T_ + rg0) * C_ + h * D_;
    uint32_t* y1 = g_y32 + (size_t)(b * T_ + rg0 + 8) * C_ + h * D_;
    #pragma unroll
    for (int nf = 0; nf < 8; ++nf) {
        *(uint2*)&y0[nf * 8 + 2 * tig] =
            make_uint2(f2tf32(oacc[nf][0] * i0), f2tf32(oacc[nf][1] * i0));
        *(uint2*)&y1[nf * 8 + 2 * tig] =
            make_uint2(f2tf32(oacc[nf][2] * i1), f2tf32(oacc[nf][3] * i1));
    }
}

// ---------------------------------------------------------------------------
extern "C" void kernel_launch(void* const* d_in, const int* in_sizes, int n_in,
                              void* d_out, int out_size)
{
    const float* x      = (const float*)d_in[0];
    const float* w_attn = (const float*)d_in[1];
    const float* b_attn = (const float*)d_in[2];
    const float* w_proj = (const float*)d_in[3];
    const float* b_proj = (const float*)d_in[4];
    float* out = (float*)d_out;

    cudaFuncSetAttribute(gemm_mma<0>, cudaFuncAttributeMaxDynamicSharedMemorySize, GEMM_SMEM);
    cudaFuncSetAttribute(gemm_mma<1>, cudaFuncAttributeMaxDynamicSharedMemorySize, GEMM_SMEM);
    cudaFuncSetAttribute(attn_mma, cudaFuncAttributeMaxDynamicSharedMemorySize, ATTN_SMEM_BYTES);

    // 0) pre-convert inputs to tf32
    uint32_t* px; cudaGetSymbolAddress((void**)&px, g_x32);
    uint32_t* pa; cudaGetSymbolAddress((void**)&pa, g_wa32);
    uint32_t* pp; cudaGetSymbolAddress((void**)&pp, g_wp32);
    uint32_t* py; cudaGetSymbolAddress((void**)&py, g_y32);
    conv_tf32<<<(S_*C_/4 + 255)/256, 256>>>(x, px, S_*C_/4);
    conv_tf32<<<(C_*3*C_/4 + 255)/256, 256>>>(w_attn, pa, C_*3*C_/4);
    conv_tf32<<<(C_*C_/4 + 255)/256, 256>>>(w_proj, pp, C_*C_/4);

    // 1) QKV GEMM (256x128 tiles) -> q hi/lo, k hi, v hi/lo planes
    gemm_mma<0><<<dim3(3*C_/128, S_/256), 512, GEMM_SMEM>>>(px, pa, b_attn, nullptr, 3*C_, C_);

    // 2) Tensor-core causal flash attention -> g_y32 (tf32)
    attn_mma<<<dim3(T_/BQ, H_, B_), 256, ATTN_SMEM_BYTES>>>();

    // 3) Proj GEMM (256x128 tiles) + bias -> out (fp32)
    gemm_mma<1><<<dim3(C_/128, S_/256), 512, GEMM_SMEM>>>(py, pp, b_proj, out, C_, C_);
}

// round 7
// speedup vs baseline: 4.6554x; 1.2504x over previous
#include <cuda_runtime.h>
#include <math_constants.h>
#include <cstdint>

#define B_ 4
#define T_ 2048
#define C_ 1024
#define H_ 16
#define D_ 64
#define S_ (B_*T_)   // 8192

// Scratch (device globals: allocation-free per harness rules)
__device__ uint32_t g_x32[S_*C_];       // x as tf32
__device__ uint32_t g_wa32[C_*3*C_];    // w_attn as tf32
__device__ uint32_t g_wp32[C_*C_];      // w_proj as tf32
__device__ uint32_t g_y32[S_*C_];       // attention output as tf32
// q hi/lo, k hi, v hi planes (QK = (q_hi+q_lo)*k_hi; PV = p_hi*v_hi)
__device__ uint32_t g_qhi[B_*H_*T_*D_];
__device__ uint32_t g_qlo[B_*H_*T_*D_];
__device__ uint32_t g_khi[B_*H_*T_*D_];
__device__ uint32_t g_vhi[B_*H_*T_*D_];

__device__ __forceinline__ uint32_t f2tf32(float f) {
    uint32_t r;
    asm("cvt.rna.tf32.f32 %0, %1;" : "=r"(r) : "f"(f));
    return r;
}

// mma.sync m16n8k8 tf32: D += A*B.  A row-major 16x8, B col-major 8x8.
// Frag maps (g=lane>>2, tig=lane&3):
//  A: a0=(g,tig) a1=(g+8,tig) a2=(g,tig+4) a3=(g+8,tig+4)
//  B: b0=(k=tig,n=g) b1=(k=tig+4,n=g)
//  C: c0=(g,2tig) c1=(g,2tig+1) c2=(g+8,2tig) c3=(g+8,2tig+1)
__device__ __forceinline__ void mma_tf32(float c[4],
                                         uint32_t a0, uint32_t a1, uint32_t a2, uint32_t a3,
                                         uint32_t b0, uint32_t b1) {
    asm volatile(
        "mma.sync.aligned.m16n8k8.row.col.f32.tf32.tf32.f32 "
        "{%0,%1,%2,%3}, {%4,%5,%6,%7}, {%8,%9}, {%0,%1,%2,%3};"
        : "+f"(c[0]), "+f"(c[1]), "+f"(c[2]), "+f"(c[3])
        : "r"(a0), "r"(a1), "r"(a2), "r"(a3), "r"(b0), "r"(b1));
}

// ---------------------------------------------------------------------------
// fp32 -> tf32 bulk converter
// ---------------------------------------------------------------------------
__global__ __launch_bounds__(256)
void conv_tf32(const float* __restrict__ s, uint32_t* __restrict__ d, int n4)
{
    const int i = blockIdx.x * blockDim.x + threadIdx.x;
    if (i < n4) {
        float4 v = ((const float4*)s)[i];
        uint4 w;
        w.x = f2tf32(v.x); w.y = f2tf32(v.y); w.z = f2tf32(v.z); w.w = f2tf32(v.w);
        ((uint4*)d)[i] = w;
    }
}

// ---------------------------------------------------------------------------
// TF32 tensor-core GEMM (R5 config: 128x128 CTA, 256 thr, 2 CTAs/SM,
// cp.async 3-stage). A smem [m][k] pad 36, B smem [k][n] pad 136.
// MODE 0: epilogue -> q hi/lo, k hi, v hi planes (q pre-scaled by 1/8).
// MODE 1: epilogue -> fp32 out + bias.
// ---------------------------------------------------------------------------
#define PA 36
#define PB 136
#define AW (128*PA)          // 4608 words
#define BW (32*PB)           // 4352 words
#define STW (AW+BW)          // 8960 words per stage
#define GEMM_SMEM (3*STW*4)  // 107520 B

template<int MODE>
__global__ __launch_bounds__(256, 2)
void gemm_mma(const uint32_t* __restrict__ A32,
              const uint32_t* __restrict__ W32,
              const float* __restrict__ bias,
              float* __restrict__ out,
              int N, int K)
{
    extern __shared__ uint32_t sm4[];
    uint32_t sbase;
    asm("{ .reg .u64 t; cvta.to.shared.u64 t, %1; cvt.u32.u64 %0, t; }"
        : "=r"(sbase) : "l"(sm4));

    const int tid = threadIdx.x;
    const int wid = tid >> 5, lane = tid & 31;
    const int g = lane >> 2, tig = lane & 3;
    const int wm = (wid & 1) * 64;
    const int wn = (wid >> 1) * 32;
    const int bm = blockIdx.y * 128, bn = blockIdx.x * 128;

    float acc[4][4][4];
    #pragma unroll
    for (int i = 0; i < 4; ++i)
        #pragma unroll
        for (int j = 0; j < 4; ++j)
            #pragma unroll
            for (int k = 0; k < 4; ++k) acc[i][j][k] = 0.f;

    const int nch = K / 32;

    auto ISSUE = [&](int c, int st) {
        const int k0 = c * 32;
        const uint32_t so = st * STW;
        #pragma unroll
        for (int i = 0; i < 4; ++i) {              // A: 128 rows x 32 k
            const int idx = tid + i * 256;
            const int row = idx >> 3, kq = idx & 7;
            const uint32_t* src = A32 + (size_t)(bm + row) * K + k0 + kq * 4;
            const uint32_t dst = sbase + (so + row * PA + kq * 4) * 4;
            asm volatile("cp.async.cg.shared.global [%0], [%1], 16;"
                         :: "r"(dst), "l"(src) : "memory");
        }
        #pragma unroll
        for (int i = 0; i < 4; ++i) {              // B: 32 k-rows x 128 n
            const int idx = tid + i * 256;
            const int kr = idx >> 5, n4 = (idx & 31) << 2;
            const uint32_t* src = W32 + (size_t)(k0 + kr) * N + bn + n4;
            const uint32_t dst = sbase + (so + AW + kr * PB + n4) * 4;
            asm volatile("cp.async.cg.shared.global [%0], [%1], 16;"
                         :: "r"(dst), "l"(src) : "memory");
        }
        asm volatile("cp.async.commit_group;" ::: "memory");
    };

    auto COMPUTE = [&](int st) {
        const uint32_t* As = sm4 + st * STW;
        const uint32_t* Bs = As + AW;
        #pragma unroll
        for (int ks = 0; ks < 4; ++ks) {
            uint32_t af[4][4];
            #pragma unroll
            for (int mf = 0; mf < 4; ++mf) {
                const int r0 = wm + mf * 16 + g;
                af[mf][0] = As[r0 * PA + ks * 8 + tig];
                af[mf][1] = As[(r0 + 8) * PA + ks * 8 + tig];
                af[mf][2] = As[r0 * PA + ks * 8 + tig + 4];
                af[mf][3] = As[(r0 + 8) * PA + ks * 8 + tig + 4];
            }
            uint32_t bf[4][2];
            #pragma unroll
            for (int nf = 0; nf < 4; ++nf) {
                const int n0 = wn + nf * 8 + g;
                bf[nf][0] = Bs[(ks * 8 + tig) * PB + n0];
                bf[nf][1] = Bs[(ks * 8 + tig + 4) * PB + n0];
            }
            #pragma unroll
            for (int mf = 0; mf < 4; ++mf)
                #pragma unroll
                for (int nf = 0; nf < 4; ++nf)
                    mma_tf32(acc[mf][nf], af[mf][0], af[mf][1], af[mf][2], af[mf][3],
                             bf[nf][0], bf[nf][1]);
        }
    };

    ISSUE(0, 0);
    ISSUE(1, 1);
    for (int c = 0; c < nch; ++c) {
        if (c + 1 < nch) asm volatile("cp.async.wait_group 1;" ::: "memory");
        else             asm volatile("cp.async.wait_group 0;" ::: "memory");
        __syncthreads();
        COMPUTE(c % 3);
        if (c + 2 < nch) ISSUE(c + 2, (c + 2) % 3);
    }

    #pragma unroll
    for (int mf = 0; mf < 4; ++mf) {
        const int r0 = bm + wm + mf * 16 + g;
        #pragma unroll
        for (int nf = 0; nf < 4; ++nf) {
            const int n0 = bn + wn + nf * 8 + tig * 2;
            const float bv0 = bias[n0], bv1 = bias[n0 + 1];
            float v00 = acc[mf][nf][0] + bv0, v01 = acc[mf][nf][1] + bv1;
            float v10 = acc[mf][nf][2] + bv0, v11 = acc[mf][nf][3] + bv1;
            if (MODE == 0) {
                const int part = n0 >> 10;               // 0:q 1:k 2:v
                const int cl = n0 & 1023;
                const int hh = cl >> 6, dd = cl & 63;
                const int bb0 = r0 >> 11, tt0 = r0 & 2047;
                const int r1 = r0 + 8;
                const int bb1 = r1 >> 11, tt1 = r1 & 2047;
                const int i0 = ((((bb0 * H_ + hh) * T_) + tt0) << 6) + dd;
                const int i1 = ((((bb1 * H_ + hh) * T_) + tt1) << 6) + dd;
                if (part == 0) {
                    v00 *= 0.125f; v01 *= 0.125f; v10 *= 0.125f; v11 *= 0.125f;
                    const uint32_t h00 = f2tf32(v00), h01 = f2tf32(v01);
                    const uint32_t h10 = f2tf32(v10), h11 = f2tf32(v11);
                    *(uint2*)&g_qhi[i0] = make_uint2(h00, h01);
                    *(uint2*)&g_qhi[i1] = make_uint2(h10, h11);
                    *(uint2*)&g_qlo[i0] = make_uint2(f2tf32(v00 - __uint_as_float(h00)),
                                                     f2tf32(v01 - __uint_as_float(h01)));
                    *(uint2*)&g_qlo[i1] = make_uint2(f2tf32(v10 - __uint_as_float(h10)),
                                                     f2tf32(v11 - __uint_as_float(h11)));
                } else if (part == 1) {
                    *(uint2*)&g_khi[i0] = make_uint2(f2tf32(v00), f2tf32(v01));
                    *(uint2*)&g_khi[i1] = make_uint2(f2tf32(v10), f2tf32(v11));
                } else {
                    *(uint2*)&g_vhi[i0] = make_uint2(f2tf32(v00), f2tf32(v01));
                    *(uint2*)&g_vhi[i1] = make_uint2(f2tf32(v10), f2tf32(v11));
                }
            } else {
                *(float2*)&out[(size_t)r0 * N + n0]       = make_float2(v00, v01);
                *(float2*)&out[(size_t)(r0 + 8) * N + n0] = make_float2(v10, v11);
            }
        }
    }
}

// ---------------------------------------------------------------------------
// Tensor-core causal flash attention.
// QK: 2-term ((q_hi+q_lo)*k_hi); PV: 1-term (p_hi*v_hi). K/V tiles of 64
// rows, 2 planes (khi,vhi), cp.async double-buffered. P stored as tf32.
// Strides: K plane 68 (bank 4g+tig), V plane 72 (bank 8tig+g), P 68.
// Big q-tiles launch first for wave balance.
// ---------------------------------------------------------------------------
#define BQ 128
#define PWK 68
#define PWV 72
#define PWP 68
#define KPW (64*PWK)            // 4352 words (k_hi plane)
#define VPW (64*PWV)            // 4608 words (v_hi plane)
#define BUFW (KPW + VPW)        // 8960 words per buffer
#define PS_OFF (2*BUFW)         // 17920
#define ATTN_SMEM_BYTES ((PS_OFF + BQ*PWP)*4)   // 106496 B

__global__ __launch_bounds__(256, 1)
void attn_mma()
{
    extern __shared__ uint32_t sw[];
    uint32_t sbase;
    asm("{ .reg .u64 t; cvta.to.shared.u64 t, %1; cvt.u32.u64 %0, t; }"
        : "=r"(sbase) : "l"(sw));

    const int tid = threadIdx.x, wid = tid >> 5, lane = tid & 31;
    const int g = lane >> 2, tig = lane & 3;
    const int qt = gridDim.x - 1 - blockIdx.x;   // big tiles first
    const int h = blockIdx.y, b = blockIdx.z;
    const int qbase = qt * BQ;
    const size_t pb = (size_t)((b * H_ + h) * T_) * D_;

    // Q fragments (hi/lo), register-resident: rows qbase+wid*16+{g,g+8}
    uint32_t aqh[8][4], aql[8][4];
    {
        const uint32_t* qh = g_qhi + pb;
        const uint32_t* ql = g_qlo + pb;
        const int r0 = qbase + wid * 16 + g;
        #pragma unroll
        for (int ks = 0; ks < 8; ++ks) {
            const int c = ks * 8 + tig;
            aqh[ks][0] = qh[(size_t)r0 * 64 + c];
            aqh[ks][1] = qh[(size_t)(r0 + 8) * 64 + c];
            aqh[ks][2] = qh[(size_t)r0 * 64 + c + 4];
            aqh[ks][3] = qh[(size_t)(r0 + 8) * 64 + c + 4];
            aql[ks][0] = ql[(size_t)r0 * 64 + c];
            aql[ks][1] = ql[(size_t)(r0 + 8) * 64 + c];
            aql[ks][2] = ql[(size_t)r0 * 64 + c + 4];
            aql[ks][3] = ql[(size_t)(r0 + 8) * 64 + c + 4];
        }
    }

    float oacc[8][4];
    #pragma unroll
    for (int nf = 0; nf < 8; ++nf)
        #pragma unroll
        for (int j = 0; j < 4; ++j) oacc[nf][j] = 0.f;
    float m0 = -CUDART_INF_F, m1 = -CUDART_INF_F, l0 = 0.f, l1 = 0.f;

    const int nkt = 2 * qt + 2;

    auto ISSUE = [&](int kt, int buf) {
        const uint32_t bufo = buf * BUFW;
        #pragma unroll
        for (int p = 0; p < 2; ++p) {
            const uint32_t* plane = (p == 0) ? g_khi : g_vhi;
            const uint32_t pofs = (p == 0) ? 0u : (uint32_t)KPW;
            const int str = (p == 0) ? PWK : PWV;
            #pragma unroll
            for (int i = 0; i < 4; ++i) {
                const int idx = tid + i * 256;
                const int row = idx >> 4, c4 = (idx & 15) << 2;
                const uint32_t* src = plane + pb + (size_t)(kt * 64 + row) * 64 + c4;
                const uint32_t dst = sbase + (bufo + pofs + row * str + c4) * 4;
                asm volatile("cp.async.cg.shared.global [%0], [%1], 16;"
                             :: "r"(dst), "l"(src) : "memory");
            }
        }
        asm volatile("cp.async.commit_group;" ::: "memory");
    };

    ISSUE(0, 0);
    if (nkt > 1) ISSUE(1, 1);

    for (int kt = 0; kt < nkt; ++kt) {
        if (kt < nkt - 1) asm volatile("cp.async.wait_group 1;" ::: "memory");
        else              asm volatile("cp.async.wait_group 0;" ::: "memory");
        __syncthreads();

        const uint32_t* KH = sw + (kt & 1) * BUFW;
        const uint32_t* VH = KH + KPW;
        uint32_t* Ps = sw + PS_OFF;     // P as tf32 bits

        // ---- S = Q K^T:  (q_hi + q_lo) * k_hi ----
        float sa[8][4];
        #pragma unroll
        for (int nf = 0; nf < 8; ++nf)
            #pragma unroll
            for (int j = 0; j < 4; ++j) sa[nf][j] = 0.f;
        #pragma unroll
        for (int ks = 0; ks < 8; ++ks) {
            #pragma unroll
            for (int nf = 0; nf < 8; ++nf) {
                const int bo = (nf * 8 + g) * PWK + ks * 8 + tig;
                const uint32_t bh0 = KH[bo], bh1 = KH[bo + 4];
                mma_tf32(sa[nf], aqh[ks][0], aqh[ks][1], aqh[ks][2], aqh[ks][3], bh0, bh1);
                mma_tf32(sa[nf], aql[ks][0], aql[ks][1], aql[ks][2], aql[ks][3], bh0, bh1);
            }
        }

        // ---- causal mask ----
        const int ktb = kt * 64;
        const int rg0 = qbase + wid * 16 + g, rg1 = rg0 + 8;
        if (ktb >= qbase) {
            #pragma unroll
            for (int nf = 0; nf < 8; ++nf) {
                const int c0 = ktb + nf * 8 + 2 * tig;
                if (c0     > rg0) sa[nf][0] = -CUDART_INF_F;
                if (c0 + 1 > rg0) sa[nf][1] = -CUDART_INF_F;
                if (c0     > rg1) sa[nf][2] = -CUDART_INF_F;
                if (c0 + 1 > rg1) sa[nf][3] = -CUDART_INF_F;
            }
        }

        // ---- running softmax ----
        float mt0 = -CUDART_INF_F, mt1 = -CUDART_INF_F;
        #pragma unroll
        for (int nf = 0; nf < 8; ++nf) {
            mt0 = fmaxf(mt0, fmaxf(sa[nf][0], sa[nf][1]));
            mt1 = fmaxf(mt1, fmaxf(sa[nf][2], sa[nf][3]));
        }
        mt0 = fmaxf(mt0, __shfl_xor_sync(0xffffffffu, mt0, 1));
        mt0 = fmaxf(mt0, __shfl_xor_sync(0xffffffffu, mt0, 2));
        mt1 = fmaxf(mt1, __shfl_xor_sync(0xffffffffu, mt1, 1));
        mt1 = fmaxf(mt1, __shfl_xor_sync(0xffffffffu, mt1, 2));
        const float mn0 = fmaxf(m0, mt0), mn1 = fmaxf(m1, mt1);
        const float al0 = __expf(m0 - mn0), al1 = __expf(m1 - mn1);
        float ls0 = 0.f, ls1 = 0.f;
        const int prow = wid * 16 + g;
        #pragma unroll
        for (int nf = 0; nf < 8; ++nf) {
            const float p0 = __expf(sa[nf][0] - mn0), p1 = __expf(sa[nf][1] - mn0);
            const float p2 = __expf(sa[nf][2] - mn1), p3 = __expf(sa[nf][3] - mn1);
            ls0 += p0 + p1; ls1 += p2 + p3;
            *(uint2*)&Ps[prow * PWP + nf * 8 + 2 * tig] =
                make_uint2(f2tf32(p0), f2tf32(p1));
            *(uint2*)&Ps[(prow + 8) * PWP + nf * 8 + 2 * tig] =
                make_uint2(f2tf32(p2), f2tf32(p3));
        }
        ls0 += __shfl_xor_sync(0xffffffffu, ls0, 1);
        ls0 += __shfl_xor_sync(0xffffffffu, ls0, 2);
        ls1 += __shfl_xor_sync(0xffffffffu, ls1, 1);
        ls1 += __shfl_xor_sync(0xffffffffu, ls1, 2);
        l0 = l0 * al0 + ls0;
        l1 = l1 * al1 + ls1;
        m0 = mn0; m1 = mn1;
        #pragma unroll
        for (int nf = 0; nf < 8; ++nf) {
            oacc[nf][0] *= al0; oacc[nf][1] *= al0;
            oacc[nf][2] *= al1; oacc[nf][3] *= al1;
        }
        __syncwarp();   // P rows are warp-private

        // ---- O += P V (single term: p_hi * v_hi) ----
        #pragma unroll
        for (int ks = 0; ks < 8; ++ks) {
            const int kc = ks * 8 + tig;
            const uint32_t ph0 = Ps[prow * PWP + kc];
            const uint32_t ph1 = Ps[(prow + 8) * PWP + kc];
            const uint32_t ph2 = Ps[prow * PWP + kc + 4];
            const uint32_t ph3 = Ps[(prow + 8) * PWP + kc + 4];
            #pragma unroll
            for (int nf = 0; nf < 8; ++nf) {
                const int vo = kc * PWV + nf * 8 + g;
                mma_tf32(oacc[nf], ph0, ph1, ph2, ph3, VH[vo], VH[vo + 4 * PWV]);
            }
        }

        __syncthreads();
        if (kt + 2 < nkt) ISSUE(kt + 2, kt & 1);
    }

    // ---- finalize: y (tf32) for the proj GEMM ----
    const float i0 = __frcp_rn(l0), i1 = __frcp_rn(l1);
    const int rg0 = qbase + wid * 16 + g;
    uint32_t* y0 = g_y32 + (size_t)(b * T_ + rg0) * C_ + h * D_;
    uint32_t* y1 = g_y32 + (size_t)(b * T_ + rg0 + 8) * C_ + h * D_;
    #pragma unroll
    for (int nf = 0; nf < 8; ++nf) {
        *(uint2*)&y0[nf * 8 + 2 * tig] =
            make_uint2(f2tf32(oacc[nf][0] * i0), f2tf32(oacc[nf][1] * i0));
        *(uint2*)&y1[nf * 8 + 2 * tig] =
            make_uint2(f2tf32(oacc[nf][2] * i1), f2tf32(oacc[nf][3] * i1));
    }
}

// ---------------------------------------------------------------------------
extern "C" void kernel_launch(void* const* d_in, const int* in_sizes, int n_in,
                              void* d_out, int out_size)
{
    const float* x      = (const float*)d_in[0];
    const float* w_attn = (const float*)d_in[1];
    const float* b_attn = (const float*)d_in[2];
    const float* w_proj = (const float*)d_in[3];
    const float* b_proj = (const float*)d_in[4];
    float* out = (float*)d_out;

    cudaFuncSetAttribute(gemm_mma<0>, cudaFuncAttributeMaxDynamicSharedMemorySize, GEMM_SMEM);
    cudaFuncSetAttribute(gemm_mma<1>, cudaFuncAttributeMaxDynamicSharedMemorySize, GEMM_SMEM);
    cudaFuncSetAttribute(attn_mma, cudaFuncAttributeMaxDynamicSharedMemorySize, ATTN_SMEM_BYTES);

    // 0) pre-convert inputs to tf32
    uint32_t* px; cudaGetSymbolAddress((void**)&px, g_x32);
    uint32_t* pa; cudaGetSymbolAddress((void**)&pa, g_wa32);
    uint32_t* pp; cudaGetSymbolAddress((void**)&pp, g_wp32);
    uint32_t* py; cudaGetSymbolAddress((void**)&py, g_y32);
    conv_tf32<<<(S_*C_/4 + 255)/256, 256>>>(x, px, S_*C_/4);
    conv_tf32<<<(C_*3*C_/4 + 255)/256, 256>>>(w_attn, pa, C_*3*C_/4);
    conv_tf32<<<(C_*C_/4 + 255)/256, 256>>>(w_proj, pp, C_*C_/4);

    // 1) QKV GEMM (128x128 tiles, 2 CTAs/SM) -> q hi/lo, k hi, v hi planes
    gemm_mma<0><<<dim3(3*C_/128, S_/128), 256, GEMM_SMEM>>>(px, pa, b_attn, nullptr, 3*C_, C_);

    // 2) Tensor-core causal flash attention -> g_y32 (tf32)
    attn_mma<<<dim3(T_/BQ, H_, B_), 256, ATTN_SMEM_BYTES>>>();

    // 3) Proj GEMM + bias -> out (fp32)
    gemm_mma<1><<<dim3(C_/128, S_/128), 256, GEMM_SMEM>>>(py, pp, b_proj, out, C_, C_);
}

// round 8
// speedup vs baseline: 5.1513x; 1.1065x over previous
#include <cuda_runtime.h>
#include <math_constants.h>
#include <cstdint>

#define B_ 4
#define T_ 2048
#define C_ 1024
#define H_ 16
#define D_ 64
#define S_ (B_*T_)   // 8192

// Scratch (device globals: allocation-free per harness rules)
__device__ uint32_t g_x32[S_*C_];       // x as tf32
__device__ uint32_t g_wa32[C_*3*C_];    // w_attn as tf32
__device__ uint32_t g_wp32[C_*C_];      // w_proj as tf32
__device__ uint32_t g_y32[S_*C_];       // attention output as tf32
// q/k/v single tf32 planes (QK = q_hi*k_hi; PV = p_hi*v_hi)
__device__ uint32_t g_qhi[B_*H_*T_*D_];
__device__ uint32_t g_khi[B_*H_*T_*D_];
__device__ uint32_t g_vhi[B_*H_*T_*D_];

__device__ __forceinline__ uint32_t f2tf32(float f) {
    uint32_t r;
    asm("cvt.rna.tf32.f32 %0, %1;" : "=r"(r) : "f"(f));
    return r;
}

// mma.sync m16n8k8 tf32: D += A*B.  A row-major 16x8, B col-major 8x8.
// Frag maps (g=lane>>2, tig=lane&3):
//  A: a0=(g,tig) a1=(g+8,tig) a2=(g,tig+4) a3=(g+8,tig+4)
//  B: b0=(k=tig,n=g) b1=(k=tig+4,n=g)
//  C: c0=(g,2tig) c1=(g,2tig+1) c2=(g+8,2tig) c3=(g+8,2tig+1)
__device__ __forceinline__ void mma_tf32(float c[4],
                                         uint32_t a0, uint32_t a1, uint32_t a2, uint32_t a3,
                                         uint32_t b0, uint32_t b1) {
    asm volatile(
        "mma.sync.aligned.m16n8k8.row.col.f32.tf32.tf32.f32 "
        "{%0,%1,%2,%3}, {%4,%5,%6,%7}, {%8,%9}, {%0,%1,%2,%3};"
        : "+f"(c[0]), "+f"(c[1]), "+f"(c[2]), "+f"(c[3])
        : "r"(a0), "r"(a1), "r"(a2), "r"(a3), "r"(b0), "r"(b1));
}

// ---------------------------------------------------------------------------
// fp32 -> tf32 bulk converter
// ---------------------------------------------------------------------------
__global__ __launch_bounds__(256)
void conv_tf32(const float* __restrict__ s, uint32_t* __restrict__ d, int n4)
{
    const int i = blockIdx.x * blockDim.x + threadIdx.x;
    if (i < n4) {
        float4 v = ((const float4*)s)[i];
        uint4 w;
        w.x = f2tf32(v.x); w.y = f2tf32(v.y); w.z = f2tf32(v.z); w.w = f2tf32(v.w);
        ((uint4*)d)[i] = w;
    }
}

// ---------------------------------------------------------------------------
// TF32 tensor-core GEMM (128x128 CTA, 256 thr, 2 CTAs/SM, cp.async 3-stage).
// A smem [m][k] pad 36, B smem [k][n] pad 136.
// MODE 0: epilogue -> q (scaled 1/8), k, v single tf32 planes.
// MODE 1: epilogue -> fp32 out + bias.
// ---------------------------------------------------------------------------
#define PA 36
#define PB 136
#define AW (128*PA)          // 4608 words
#define BW (32*PB)           // 4352 words
#define STW (AW+BW)          // 8960 words per stage
#define GEMM_SMEM (3*STW*4)  // 107520 B

template<int MODE>
__global__ __launch_bounds__(256, 2)
void gemm_mma(const uint32_t* __restrict__ A32,
              const uint32_t* __restrict__ W32,
              const float* __restrict__ bias,
              float* __restrict__ out,
              int N, int K)
{
    extern __shared__ uint32_t sm4[];
    uint32_t sbase;
    asm("{ .reg .u64 t; cvta.to.shared.u64 t, %1; cvt.u32.u64 %0, t; }"
        : "=r"(sbase) : "l"(sm4));

    const int tid = threadIdx.x;
    const int wid = tid >> 5, lane = tid & 31;
    const int g = lane >> 2, tig = lane & 3;
    const int wm = (wid & 1) * 64;
    const int wn = (wid >> 1) * 32;
    const int bm = blockIdx.y * 128, bn = blockIdx.x * 128;

    float acc[4][4][4];
    #pragma unroll
    for (int i = 0; i < 4; ++i)
        #pragma unroll
        for (int j = 0; j < 4; ++j)
            #pragma unroll
            for (int k = 0; k < 4; ++k) acc[i][j][k] = 0.f;

    const int nch = K / 32;

    auto ISSUE = [&](int c, int st) {
        const int k0 = c * 32;
        const uint32_t so = st * STW;
        #pragma unroll
        for (int i = 0; i < 4; ++i) {              // A: 128 rows x 32 k
            const int idx = tid + i * 256;
            const int row = idx >> 3, kq = idx & 7;
            const uint32_t* src = A32 + (size_t)(bm + row) * K + k0 + kq * 4;
            const uint32_t dst = sbase + (so + row * PA + kq * 4) * 4;
            asm volatile("cp.async.cg.shared.global [%0], [%1], 16;"
                         :: "r"(dst), "l"(src) : "memory");
        }
        #pragma unroll
        for (int i = 0; i < 4; ++i) {              // B: 32 k-rows x 128 n
            const int idx = tid + i * 256;
            const int kr = idx >> 5, n4 = (idx & 31) << 2;
            const uint32_t* src = W32 + (size_t)(k0 + kr) * N + bn + n4;
            const uint32_t dst = sbase + (so + AW + kr * PB + n4) * 4;
            asm volatile("cp.async.cg.shared.global [%0], [%1], 16;"
                         :: "r"(dst), "l"(src) : "memory");
        }
        asm volatile("cp.async.commit_group;" ::: "memory");
    };

    auto COMPUTE = [&](int st) {
        const uint32_t* As = sm4 + st * STW;
        const uint32_t* Bs = As + AW;
        #pragma unroll
        for (int ks = 0; ks < 4; ++ks) {
            uint32_t af[4][4];
            #pragma unroll
            for (int mf = 0; mf < 4; ++mf) {
                const int r0 = wm + mf * 16 + g;
                af[mf][0] = As[r0 * PA + ks * 8 + tig];
                af[mf][1] = As[(r0 + 8) * PA + ks * 8 + tig];
                af[mf][2] = As[r0 * PA + ks * 8 + tig + 4];
                af[mf][3] = As[(r0 + 8) * PA + ks * 8 + tig + 4];
            }
            uint32_t bf[4][2];
            #pragma unroll
            for (int nf = 0; nf < 4; ++nf) {
                const int n0 = wn + nf * 8 + g;
                bf[nf][0] = Bs[(ks * 8 + tig) * PB + n0];
                bf[nf][1] = Bs[(ks * 8 + tig + 4) * PB + n0];
            }
            #pragma unroll
            for (int mf = 0; mf < 4; ++mf)
                #pragma unroll
                for (int nf = 0; nf < 4; ++nf)
                    mma_tf32(acc[mf][nf], af[mf][0], af[mf][1], af[mf][2], af[mf][3],
                             bf[nf][0], bf[nf][1]);
        }
    };

    ISSUE(0, 0);
    ISSUE(1, 1);
    for (int c = 0; c < nch; ++c) {
        if (c + 1 < nch) asm volatile("cp.async.wait_group 1;" ::: "memory");
        else             asm volatile("cp.async.wait_group 0;" ::: "memory");
        __syncthreads();
        COMPUTE(c % 3);
        if (c + 2 < nch) ISSUE(c + 2, (c + 2) % 3);
    }

    #pragma unroll
    for (int mf = 0; mf < 4; ++mf) {
        const int r0 = bm + wm + mf * 16 + g;
        #pragma unroll
        for (int nf = 0; nf < 4; ++nf) {
            const int n0 = bn + wn + nf * 8 + tig * 2;
            const float bv0 = bias[n0], bv1 = bias[n0 + 1];
            float v00 = acc[mf][nf][0] + bv0, v01 = acc[mf][nf][1] + bv1;
            float v10 = acc[mf][nf][2] + bv0, v11 = acc[mf][nf][3] + bv1;
            if (MODE == 0) {
                const int part = n0 >> 10;               // 0:q 1:k 2:v
                const int cl = n0 & 1023;
                const int hh = cl >> 6, dd = cl & 63;
                const int bb0 = r0 >> 11, tt0 = r0 & 2047;
                const int r1 = r0 + 8;
                const int bb1 = r1 >> 11, tt1 = r1 & 2047;
                const int i0 = ((((bb0 * H_ + hh) * T_) + tt0) << 6) + dd;
                const int i1 = ((((bb1 * H_ + hh) * T_) + tt1) << 6) + dd;
                uint32_t* dst;
                if (part == 0) {
                    dst = g_qhi;
                    v00 *= 0.125f; v01 *= 0.125f; v10 *= 0.125f; v11 *= 0.125f;
                } else dst = (part == 1) ? g_khi : g_vhi;
                *(uint2*)&dst[i0] = make_uint2(f2tf32(v00), f2tf32(v01));
                *(uint2*)&dst[i1] = make_uint2(f2tf32(v10), f2tf32(v11));
            } else {
                *(float2*)&out[(size_t)r0 * N + n0]       = make_float2(v00, v01);
                *(float2*)&out[(size_t)(r0 + 8) * N + n0] = make_float2(v10, v11);
            }
        }
    }
}

// ---------------------------------------------------------------------------
// Tensor-core causal flash attention.
// QK: single-term q_hi*k_hi; PV: single-term p_hi*v_hi. K/V tiles of 64
// rows, 2 planes (khi,vhi), cp.async double-buffered, 2 CTAs/SM.
// Strides: K plane 68 (bank 4g+tig), V plane 72 (bank 8tig+g), P 68.
// Big q-tiles launch first for wave balance.
// ---------------------------------------------------------------------------
#define BQ 128
#define PWK 68
#define PWV 72
#define PWP 68
#define KPW (64*PWK)            // 4352 words (k plane)
#define VPW (64*PWV)            // 4608 words (v plane)
#define BUFW (KPW + VPW)        // 8960 words per buffer
#define PS_OFF (2*BUFW)         // 17920
#define ATTN_SMEM_BYTES ((PS_OFF + BQ*PWP)*4)   // 106496 B

__global__ __launch_bounds__(256, 2)
void attn_mma()
{
    extern __shared__ uint32_t sw[];
    uint32_t sbase;
    asm("{ .reg .u64 t; cvta.to.shared.u64 t, %1; cvt.u32.u64 %0, t; }"
        : "=r"(sbase) : "l"(sw));

    const int tid = threadIdx.x, wid = tid >> 5, lane = tid & 31;
    const int g = lane >> 2, tig = lane & 3;
    const int qt = gridDim.x - 1 - blockIdx.x;   // big tiles first
    const int h = blockIdx.y, b = blockIdx.z;
    const int qbase = qt * BQ;
    const size_t pb = (size_t)((b * H_ + h) * T_) * D_;

    // Q fragments, register-resident: rows qbase+wid*16+{g,g+8}
    uint32_t aqh[8][4];
    {
        const uint32_t* qh = g_qhi + pb;
        const int r0 = qbase + wid * 16 + g;
        #pragma unroll
        for (int ks = 0; ks < 8; ++ks) {
            const int c = ks * 8 + tig;
            aqh[ks][0] = qh[(size_t)r0 * 64 + c];
            aqh[ks][1] = qh[(size_t)(r0 + 8) * 64 + c];
            aqh[ks][2] = qh[(size_t)r0 * 64 + c + 4];
            aqh[ks][3] = qh[(size_t)(r0 + 8) * 64 + c + 4];
        }
    }

    float oacc[8][4];
    #pragma unroll
    for (int nf = 0; nf < 8; ++nf)
        #pragma unroll
        for (int j = 0; j < 4; ++j) oacc[nf][j] = 0.f;
    float m0 = -CUDART_INF_F, m1 = -CUDART_INF_F, l0 = 0.f, l1 = 0.f;

    const int nkt = 2 * qt + 2;

    auto ISSUE = [&](int kt, int buf) {
        const uint32_t bufo = buf * BUFW;
        #pragma unroll
        for (int p = 0; p < 2; ++p) {
            const uint32_t* plane = (p == 0) ? g_khi : g_vhi;
            const uint32_t pofs = (p == 0) ? 0u : (uint32_t)KPW;
            const int str = (p == 0) ? PWK : PWV;
            #pragma unroll
            for (int i = 0; i < 4; ++i) {
                const int idx = tid + i * 256;
                const int row = idx >> 4, c4 = (idx & 15) << 2;
                const uint32_t* src = plane + pb + (size_t)(kt * 64 + row) * 64 + c4;
                const uint32_t dst = sbase + (bufo + pofs + row * str + c4) * 4;
                asm volatile("cp.async.cg.shared.global [%0], [%1], 16;"
                             :: "r"(dst), "l"(src) : "memory");
            }
        }
        asm volatile("cp.async.commit_group;" ::: "memory");
    };

    ISSUE(0, 0);
    if (nkt > 1) ISSUE(1, 1);

    for (int kt = 0; kt < nkt; ++kt) {
        if (kt < nkt - 1) asm volatile("cp.async.wait_group 1;" ::: "memory");
        else              asm volatile("cp.async.wait_group 0;" ::: "memory");
        __syncthreads();

        const uint32_t* KH = sw + (kt & 1) * BUFW;
        const uint32_t* VH = KH + KPW;
        uint32_t* Ps = sw + PS_OFF;     // P as tf32 bits

        // ---- S = Q K^T (single term) ----
        float sa[8][4];
        #pragma unroll
        for (int nf = 0; nf < 8; ++nf)
            #pragma unroll
            for (int j = 0; j < 4; ++j) sa[nf][j] = 0.f;
        #pragma unroll
        for (int ks = 0; ks < 8; ++ks) {
            #pragma unroll
            for (int nf = 0; nf < 8; ++nf) {
                const int bo = (nf * 8 + g) * PWK + ks * 8 + tig;
                mma_tf32(sa[nf], aqh[ks][0], aqh[ks][1], aqh[ks][2], aqh[ks][3],
                         KH[bo], KH[bo + 4]);
            }
        }

        // ---- causal mask ----
        const int ktb = kt * 64;
        const int rg0 = qbase + wid * 16 + g, rg1 = rg0 + 8;
        if (ktb >= qbase) {
            #pragma unroll
            for (int nf = 0; nf < 8; ++nf) {
                const int c0 = ktb + nf * 8 + 2 * tig;
                if (c0     > rg0) sa[nf][0] = -CUDART_INF_F;
                if (c0 + 1 > rg0) sa[nf][1] = -CUDART_INF_F;
                if (c0     > rg1) sa[nf][2] = -CUDART_INF_F;
                if (c0 + 1 > rg1) sa[nf][3] = -CUDART_INF_F;
            }
        }

        // ---- running softmax ----
        float mt0 = -CUDART_INF_F, mt1 = -CUDART_INF_F;
        #pragma unroll
        for (int nf = 0; nf < 8; ++nf) {
            mt0 = fmaxf(mt0, fmaxf(sa[nf][0], sa[nf][1]));
            mt1 = fmaxf(mt1, fmaxf(sa[nf][2], sa[nf][3]));
        }
        mt0 = fmaxf(mt0, __shfl_xor_sync(0xffffffffu, mt0, 1));
        mt0 = fmaxf(mt0, __shfl_xor_sync(0xffffffffu, mt0, 2));
        mt1 = fmaxf(mt1, __shfl_xor_sync(0xffffffffu, mt1, 1));
        mt1 = fmaxf(mt1, __shfl_xor_sync(0xffffffffu, mt1, 2));
        const float mn0 = fmaxf(m0, mt0), mn1 = fmaxf(m1, mt1);
        const float al0 = __expf(m0 - mn0), al1 = __expf(m1 - mn1);
        float ls0 = 0.f, ls1 = 0.f;
        const int prow = wid * 16 + g;
        #pragma unroll
        for (int nf = 0; nf < 8; ++nf) {
            const float p0 = __expf(sa[nf][0] - mn0), p1 = __expf(sa[nf][1] - mn0);
            const float p2 = __expf(sa[nf][2] - mn1), p3 = __expf(sa[nf][3] - mn1);
            ls0 += p0 + p1; ls1 += p2 + p3;
            *(uint2*)&Ps[prow * PWP + nf * 8 + 2 * tig] =
                make_uint2(f2tf32(p0), f2tf32(p1));
            *(uint2*)&Ps[(prow + 8) * PWP + nf * 8 + 2 * tig] =
                make_uint2(f2tf32(p2), f2tf32(p3));
        }
        ls0 += __shfl_xor_sync(0xffffffffu, ls0, 1);
        ls0 += __shfl_xor_sync(0xffffffffu, ls0, 2);
        ls1 += __shfl_xor_sync(0xffffffffu, ls1, 1);
        ls1 += __shfl_xor_sync(0xffffffffu, ls1, 2);
        l0 = l0 * al0 + ls0;
        l1 = l1 * al1 + ls1;
        m0 = mn0; m1 = mn1;
        #pragma unroll
        for (int nf = 0; nf < 8; ++nf) {
            oacc[nf][0] *= al0; oacc[nf][1] *= al0;
            oacc[nf][2] *= al1; oacc[nf][3] *= al1;
        }
        __syncwarp();   // P rows are warp-private

        // ---- O += P V (single term) ----
        #pragma unroll
        for (int ks = 0; ks < 8; ++ks) {
            const int kc = ks * 8 + tig;
            const uint32_t ph0 = Ps[prow * PWP + kc];
            const uint32_t ph1 = Ps[(prow + 8) * PWP + kc];
            const uint32_t ph2 = Ps[prow * PWP + kc + 4];
            const uint32_t ph3 = Ps[(prow + 8) * PWP + kc + 4];
            #pragma unroll
            for (int nf = 0; nf < 8; ++nf) {
                const int vo = kc * PWV + nf * 8 + g;
                mma_tf32(oacc[nf], ph0, ph1, ph2, ph3, VH[vo], VH[vo + 4 * PWV]);
            }
        }

        __syncthreads();
        if (kt + 2 < nkt) ISSUE(kt + 2, kt & 1);
    }

    // ---- finalize: y (tf32) for the proj GEMM ----
    const float i0 = __frcp_rn(l0), i1 = __frcp_rn(l1);
    const int rg0 = qbase + wid * 16 + g;
    uint32_t* y0 = g_y32 + (size_t)(b * T_ + rg0) * C_ + h * D_;
    uint32_t* y1 = g_y32 + (size_t)(b * T_ + rg0 + 8) * C_ + h * D_;
    #pragma unroll
    for (int nf = 0; nf < 8; ++nf) {
        *(uint2*)&y0[nf * 8 + 2 * tig] =
            make_uint2(f2tf32(oacc[nf][0] * i0), f2tf32(oacc[nf][1] * i0));
        *(uint2*)&y1[nf * 8 + 2 * tig] =
            make_uint2(f2tf32(oacc[nf][2] * i1), f2tf32(oacc[nf][3] * i1));
    }
}

// ---------------------------------------------------------------------------
extern "C" void kernel_launch(void* const* d_in, const int* in_sizes, int n_in,
                              void* d_out, int out_size)
{
    const float* x      = (const float*)d_in[0];
    const float* w_attn = (const float*)d_in[1];
    const float* b_attn = (const float*)d_in[2];
    const float* w_proj = (const float*)d_in[3];
    const float* b_proj = (const float*)d_in[4];
    float* out = (float*)d_out;

    cudaFuncSetAttribute(gemm_mma<0>, cudaFuncAttributeMaxDynamicSharedMemorySize, GEMM_SMEM);
    cudaFuncSetAttribute(gemm_mma<1>, cudaFuncAttributeMaxDynamicSharedMemorySize, GEMM_SMEM);
    cudaFuncSetAttribute(attn_mma, cudaFuncAttributeMaxDynamicSharedMemorySize, ATTN_SMEM_BYTES);

    // 0) pre-convert inputs to tf32
    uint32_t* px; cudaGetSymbolAddress((void**)&px, g_x32);
    uint32_t* pa; cudaGetSymbolAddress((void**)&pa, g_wa32);
    uint32_t* pp; cudaGetSymbolAddress((void**)&pp, g_wp32);
    uint32_t* py; cudaGetSymbolAddress((void**)&py, g_y32);
    conv_tf32<<<(S_*C_/4 + 255)/256, 256>>>(x, px, S_*C_/4);
    conv_tf32<<<(C_*3*C_/4 + 255)/256, 256>>>(w_attn, pa, C_*3*C_/4);
    conv_tf32<<<(C_*C_/4 + 255)/256, 256>>>(w_proj, pp, C_*C_/4);

    // 1) QKV GEMM (128x128 tiles, 2 CTAs/SM) -> q/k/v tf32 planes
    gemm_mma<0><<<dim3(3*C_/128, S_/128), 256, GEMM_SMEM>>>(px, pa, b_attn, nullptr, 3*C_, C_);

    // 2) Tensor-core causal flash attention (2 CTAs/SM) -> g_y32 (tf32)
    attn_mma<<<dim3(T_/BQ, H_, B_), 256, ATTN_SMEM_BYTES>>>();

    // 3) Proj GEMM + bias -> out (fp32)
    gemm_mma<1><<<dim3(C_/128, S_/128), 256, GEMM_SMEM>>>(py, pp, b_proj, out, C_, C_);
}